// round 3
// baseline (speedup 1.0000x reference)
#include <cuda_runtime.h>

// ---------------- problem constants ----------------
constexpr int BATCH = 2;
constexpr int NSEQ  = 2048;
constexpr int DM    = 1024;
constexpr int NH    = 16;
constexpr int DH    = 64;

// ---------------- scratch (static device globals; no allocation) ----------------
// q, k stored TRANSPOSED per head: [b,h,d,n]  (so attention loads need no transpose)
// v stored [b,h,n,d]
__device__ float g_q[BATCH * NH * DH * NSEQ];
__device__ float g_k[BATCH * NH * DH * NSEQ];
__device__ float g_v[BATCH * NH * NSEQ * DH];
__device__ float g_att[BATCH * NSEQ * DM];

// =====================================================================
// Double-buffered 128x128x16 SGEMM core (256 threads, 8x8 micro-tile)
// =====================================================================

// Kernel 1: QKV GEMM  y = x @ w_qkv, scatter into q/k/v.
// column c -> which = c%3, hd = c/3, h = hd>>6, d = hd&63
__global__ __launch_bounds__(256, 2) void qkv_gemm(const float* __restrict__ A,
                                                   const float* __restrict__ Bw)
{
    constexpr int K = DM;        // 1024
    constexpr int N = 3 * DM;    // 3072
    __shared__ __align__(16) float As[2][16][132];   // [k][m], padded
    __shared__ __align__(16) float Bs[2][16][128];   // [k][n]

    const int bx = blockIdx.x;
    const int by = blockIdx.y;
    const int tid = threadIdx.x;
    const int tx = tid & 15;
    const int ty = tid >> 4;

    const float* Ab = A + (size_t)by * 128 * K;
    const float* Bb = Bw + bx * 128;

    // load indices
    const int a_row = tid >> 2;          // 0..63 (x4 over r)
    const int a_c4  = tid & 3;           // float4 col within 16-k
    const int b_row = tid >> 5;          // 0..7  (x2 over r)
    const int b_c4  = tid & 31;

    float4 ra[2], rb[2];
    float acc[8][8] = {};

    // preload tile 0
    #pragma unroll
    for (int r = 0; r < 2; r++) {
        ra[r] = *(const float4*)(Ab + (size_t)(a_row + 64 * r) * K + a_c4 * 4);
        rb[r] = *(const float4*)(Bb + (size_t)(b_row + 8 * r) * N + b_c4 * 4);
    }
    int buf = 0;
    #pragma unroll
    for (int r = 0; r < 2; r++) {
        const int ar = a_row + 64 * r;
        As[buf][a_c4 * 4 + 0][ar] = ra[r].x;
        As[buf][a_c4 * 4 + 1][ar] = ra[r].y;
        As[buf][a_c4 * 4 + 2][ar] = ra[r].z;
        As[buf][a_c4 * 4 + 3][ar] = ra[r].w;
        *(float4*)&Bs[buf][b_row + 8 * r][b_c4 * 4] = rb[r];
    }
    __syncthreads();

    for (int k0 = 0; k0 < K; k0 += 16) {
        const bool more = (k0 + 16 < K);
        if (more) {
            #pragma unroll
            for (int r = 0; r < 2; r++) {
                ra[r] = *(const float4*)(Ab + (size_t)(a_row + 64 * r) * K + k0 + 16 + a_c4 * 4);
                rb[r] = *(const float4*)(Bb + (size_t)(b_row + 8 * r + k0 + 16) * N + b_c4 * 4);
            }
        }
        #pragma unroll
        for (int kk = 0; kk < 16; kk++) {
            float4 a0 = *(const float4*)&As[buf][kk][ty * 8];
            float4 a1 = *(const float4*)&As[buf][kk][ty * 8 + 4];
            float4 b0 = *(const float4*)&Bs[buf][kk][tx * 8];
            float4 b1 = *(const float4*)&Bs[buf][kk][tx * 8 + 4];
            const float rm[8] = {a0.x,a0.y,a0.z,a0.w,a1.x,a1.y,a1.z,a1.w};
            const float rn[8] = {b0.x,b0.y,b0.z,b0.w,b1.x,b1.y,b1.z,b1.w};
            #pragma unroll
            for (int i = 0; i < 8; i++)
                #pragma unroll
                for (int j = 0; j < 8; j++)
                    acc[i][j] = fmaf(rm[i], rn[j], acc[i][j]);
        }
        if (more) {
            const int nb = buf ^ 1;
            #pragma unroll
            for (int r = 0; r < 2; r++) {
                const int ar = a_row + 64 * r;
                As[nb][a_c4 * 4 + 0][ar] = ra[r].x;
                As[nb][a_c4 * 4 + 1][ar] = ra[r].y;
                As[nb][a_c4 * 4 + 2][ar] = ra[r].z;
                As[nb][a_c4 * 4 + 3][ar] = ra[r].w;
                *(float4*)&Bs[nb][b_row + 8 * r][b_c4 * 4] = rb[r];
            }
            __syncthreads();
            buf = nb;
        }
    }

    // epilogue: scatter to g_q (transposed, scaled), g_k (transposed), g_v
    #pragma unroll
    for (int i = 0; i < 8; i++) {
        const int m = by * 128 + ty * 8 + i;
        const int bb = m >> 11;
        const int n  = m & 2047;
        #pragma unroll
        for (int j = 0; j < 8; j++) {
            const int c = bx * 128 + tx * 8 + j;
            const int which = c % 3;
            const int hd = c / 3;
            const int h = hd >> 6;
            const int d = hd & 63;
            float val = acc[i][j];
            if (which == 0) {
                // q transposed [b,h,d,n], pre-scaled by 1/sqrt(64)
                g_q[(((size_t)(bb * NH + h) * DH + d) << 11) + n] = val * 0.125f;
            } else if (which == 1) {
                g_k[(((size_t)(bb * NH + h) * DH + d) << 11) + n] = val;
            } else {
                g_v[((((size_t)(bb * NH + h)) << 11) + n) * DH + d] = val;
            }
        }
    }
}

// =====================================================================
// Kernel 2: causal flash attention, 64q x 64k tiles, swizzled smem.
// All smem tiles are [64 rows][16 float4 cells], cell ^= (row>>2)&15.
// 256 threads: tx = tid&15 (4 cols each), ty = tid>>4 (4 rows each).
// =====================================================================
__global__ __launch_bounds__(256, 2) void attn_kernel()
{
    extern __shared__ __align__(16) float4 sm4[];
    float4* Qt = sm4;              // [d][q]
    float4* Kt = Qt + 64 * 16;     // [d][k]
    float4* Vt = Kt + 64 * 16;     // [k][d]
    float4* Pt = Vt + 64 * 16;     // [k][q]

    const int qt = (int)gridDim.x - 1 - (int)blockIdx.x;   // big tiles first
    const int bh = blockIdx.y;
    const int bb = bh >> 4, hh = bh & 15;
    const float* Qg = g_q + (size_t)bh * DH * NSEQ;   // [d][n]
    const float* Kg = g_k + (size_t)bh * DH * NSEQ;   // [d][n]
    const float* Vg = g_v + (size_t)bh * NSEQ * DH;   // [n][d]

    const int tid = threadIdx.x;
    const int tx = tid & 15;
    const int ty = tid >> 4;

    // load Q tile (rows d, cols q)
    #pragma unroll
    for (int r = 0; r < 4; r++) {
        const int idx = tid + 256 * r;
        const int d = idx >> 4, c4 = idx & 15;
        const float4 v = *(const float4*)(Qg + (size_t)d * NSEQ + qt * 64 + c4 * 4);
        Qt[d * 16 + (c4 ^ ((d >> 2) & 15))] = v;
    }

    float o[4][4] = {};
    float m[4], l[4];
    #pragma unroll
    for (int i = 0; i < 4; i++) { m[i] = -1e30f; l[i] = 0.f; }

    for (int kt = 0; kt <= qt; kt++) {
        __syncthreads();   // prior PV readers done (also covers Q-load on iter 0)
        // load K, V tiles
        #pragma unroll
        for (int r = 0; r < 4; r++) {
            const int idx = tid + 256 * r;
            const int row = idx >> 4, c4 = idx & 15;
            const int sw = (row >> 2) & 15;
            const float4 kv = *(const float4*)(Kg + (size_t)row * NSEQ + kt * 64 + c4 * 4);
            Kt[row * 16 + (c4 ^ sw)] = kv;
            const float4 vv = *(const float4*)(Vg + (size_t)(kt * 64 + row) * DH + c4 * 4);
            Vt[row * 16 + (c4 ^ sw)] = vv;
        }
        __syncthreads();

        // S = Q^T K  (rows q = ty*4+i, cols k = tx*4+j)
        float s[4][4] = {};
        #pragma unroll 8
        for (int kk = 0; kk < 64; kk++) {
            const int sw = (kk >> 2) & 15;
            const float4 q4 = Qt[kk * 16 + (ty ^ sw)];
            const float4 k4 = Kt[kk * 16 + (tx ^ sw)];
            const float qv[4] = {q4.x, q4.y, q4.z, q4.w};
            const float kv[4] = {k4.x, k4.y, k4.z, k4.w};
            #pragma unroll
            for (int i = 0; i < 4; i++)
                #pragma unroll
                for (int j = 0; j < 4; j++)
                    s[i][j] = fmaf(qv[i], kv[j], s[i][j]);
        }

        // online softmax (q pre-scaled by 1/sqrt(d))
        const bool diag = (kt == qt);
        #pragma unroll
        for (int i = 0; i < 4; i++) {
            if (diag) {
                const int grow = ty * 4 + i;      // local q index (same tile)
                #pragma unroll
                for (int j = 0; j < 4; j++)
                    if (tx * 4 + j > grow) s[i][j] = -1e30f;
            }
            float tm = fmaxf(fmaxf(s[i][0], s[i][1]), fmaxf(s[i][2], s[i][3]));
            #pragma unroll
            for (int off = 8; off > 0; off >>= 1)
                tm = fmaxf(tm, __shfl_xor_sync(0xffffffffu, tm, off));
            const float mnew = fmaxf(m[i], tm);
            const float f = __expf(m[i] - mnew);
            m[i] = mnew;
            float rs = 0.f;
            #pragma unroll
            for (int j = 0; j < 4; j++) {
                s[i][j] = __expf(s[i][j] - mnew);
                rs += s[i][j];
            }
            #pragma unroll
            for (int off = 8; off > 0; off >>= 1)
                rs += __shfl_xor_sync(0xffffffffu, rs, off);
            l[i] = l[i] * f + rs;
            #pragma unroll
            for (int j = 0; j < 4; j++) o[i][j] *= f;
        }

        // store P transposed: Pt[k][q], cell swizzle = ty ^ (row>>2) = ty ^ tx
        {
            const int cell = ty ^ tx;
            #pragma unroll
            for (int j = 0; j < 4; j++)
                Pt[(tx * 4 + j) * 16 + cell] = make_float4(s[0][j], s[1][j], s[2][j], s[3][j]);
        }
        __syncthreads();

        // O += P^T V (rows q = ty*4+i, d-cols tx*4+j)
        #pragma unroll 8
        for (int kk = 0; kk < 64; kk++) {
            const int sw = (kk >> 2) & 15;
            const float4 p4 = Pt[kk * 16 + (ty ^ sw)];
            const float4 v4 = Vt[kk * 16 + (tx ^ sw)];
            const float pv[4] = {p4.x, p4.y, p4.z, p4.w};
            const float vv[4] = {v4.x, v4.y, v4.z, v4.w};
            #pragma unroll
            for (int i = 0; i < 4; i++)
                #pragma unroll
                for (int j = 0; j < 4; j++)
                    o[i][j] = fmaf(pv[i], vv[j], o[i][j]);
        }
    }

    // normalize + store to g_att[b][n][h*64+d]
    #pragma unroll
    for (int i = 0; i < 4; i++) {
        const float inv = 1.f / l[i];
        const int n = qt * 64 + ty * 4 + i;
        float4 ov = make_float4(o[i][0] * inv, o[i][1] * inv, o[i][2] * inv, o[i][3] * inv);
        *(float4*)(g_att + ((size_t)bb * NSEQ + n) * DM + hh * 64 + tx * 4) = ov;
    }
}

// =====================================================================
// Kernel 3: output projection  out = g_att @ w_proj  [4096,1024]x[1024,1024]
// =====================================================================
__global__ __launch_bounds__(256, 2) void proj_gemm(const float* __restrict__ Bw,
                                                    float* __restrict__ C)
{
    constexpr int K = DM;
    constexpr int N = DM;
    __shared__ __align__(16) float As[2][16][132];
    __shared__ __align__(16) float Bs[2][16][128];

    const int bx = blockIdx.x;
    const int by = blockIdx.y;
    const int tid = threadIdx.x;
    const int tx = tid & 15;
    const int ty = tid >> 4;

    const float* Ab = g_att + (size_t)by * 128 * K;
    const float* Bb = Bw + bx * 128;

    const int a_row = tid >> 2;
    const int a_c4  = tid & 3;
    const int b_row = tid >> 5;
    const int b_c4  = tid & 31;

    float4 ra[2], rb[2];
    float acc[8][8] = {};

    #pragma unroll
    for (int r = 0; r < 2; r++) {
        ra[r] = *(const float4*)(Ab + (size_t)(a_row + 64 * r) * K + a_c4 * 4);
        rb[r] = *(const float4*)(Bb + (size_t)(b_row + 8 * r) * N + b_c4 * 4);
    }
    int buf = 0;
    #pragma unroll
    for (int r = 0; r < 2; r++) {
        const int ar = a_row + 64 * r;
        As[buf][a_c4 * 4 + 0][ar] = ra[r].x;
        As[buf][a_c4 * 4 + 1][ar] = ra[r].y;
        As[buf][a_c4 * 4 + 2][ar] = ra[r].z;
        As[buf][a_c4 * 4 + 3][ar] = ra[r].w;
        *(float4*)&Bs[buf][b_row + 8 * r][b_c4 * 4] = rb[r];
    }
    __syncthreads();

    for (int k0 = 0; k0 < K; k0 += 16) {
        const bool more = (k0 + 16 < K);
        if (more) {
            #pragma unroll
            for (int r = 0; r < 2; r++) {
                ra[r] = *(const float4*)(Ab + (size_t)(a_row + 64 * r) * K + k0 + 16 + a_c4 * 4);
                rb[r] = *(const float4*)(Bb + (size_t)(b_row + 8 * r + k0 + 16) * N + b_c4 * 4);
            }
        }
        #pragma unroll
        for (int kk = 0; kk < 16; kk++) {
            float4 a0 = *(const float4*)&As[buf][kk][ty * 8];
            float4 a1 = *(const float4*)&As[buf][kk][ty * 8 + 4];
            float4 b0 = *(const float4*)&Bs[buf][kk][tx * 8];
            float4 b1 = *(const float4*)&Bs[buf][kk][tx * 8 + 4];
            const float rm[8] = {a0.x,a0.y,a0.z,a0.w,a1.x,a1.y,a1.z,a1.w};
            const float rn[8] = {b0.x,b0.y,b0.z,b0.w,b1.x,b1.y,b1.z,b1.w};
            #pragma unroll
            for (int i = 0; i < 8; i++)
                #pragma unroll
                for (int j = 0; j < 8; j++)
                    acc[i][j] = fmaf(rm[i], rn[j], acc[i][j]);
        }
        if (more) {
            const int nb = buf ^ 1;
            #pragma unroll
            for (int r = 0; r < 2; r++) {
                const int ar = a_row + 64 * r;
                As[nb][a_c4 * 4 + 0][ar] = ra[r].x;
                As[nb][a_c4 * 4 + 1][ar] = ra[r].y;
                As[nb][a_c4 * 4 + 2][ar] = ra[r].z;
                As[nb][a_c4 * 4 + 3][ar] = ra[r].w;
                *(float4*)&Bs[nb][b_row + 8 * r][b_c4 * 4] = rb[r];
            }
            __syncthreads();
            buf = nb;
        }
    }

    #pragma unroll
    for (int i = 0; i < 8; i++) {
        const int mr = by * 128 + ty * 8 + i;
        float* cp = C + (size_t)mr * N + bx * 128 + tx * 8;
        *(float4*)(cp + 0) = make_float4(acc[i][0], acc[i][1], acc[i][2], acc[i][3]);
        *(float4*)(cp + 4) = make_float4(acc[i][4], acc[i][5], acc[i][6], acc[i][7]);
    }
}

// =====================================================================
extern "C" void kernel_launch(void* const* d_in, const int* in_sizes, int n_in,
                              void* d_out, int out_size)
{
    (void)in_sizes; (void)n_in; (void)out_size;
    const float* x      = (const float*)d_in[0];
    const float* w_qkv  = (const float*)d_in[1];
    const float* w_proj = (const float*)d_in[2];
    float* out = (float*)d_out;

    static bool attr_done = false;
    if (!attr_done) {
        cudaFuncSetAttribute(attn_kernel, cudaFuncAttributeMaxDynamicSharedMemorySize, 65536);
        attr_done = true;
    }

    qkv_gemm<<<dim3(24, 32), 256>>>(x, w_qkv);
    attn_kernel<<<dim3(32, 32), 256, 65536>>>();
    proj_gemm<<<dim3(8, 32), 256>>>(w_proj, out);
}

// round 4
// speedup vs baseline: 1.7673x; 1.7673x over previous
#include <cuda_runtime.h>
#include <cuda_bf16.h>
#include <cstdint>

constexpr int BATCH = 2, NSEQ = 2048, DM = 1024, NH = 16, DH = 64;
constexpr int MROWS = BATCH * NSEQ;

__device__ __nv_bfloat16 g_x_hi[MROWS*DM],     g_x_lo[MROWS*DM];
__device__ __nv_bfloat16 g_wqkv_hi[3*DM*DM],   g_wqkv_lo[3*DM*DM];   // [3072][1024] (transposed)
__device__ __nv_bfloat16 g_wp_hi[DM*DM],       g_wp_lo[DM*DM];       // [1024][1024] (transposed)
__device__ __nv_bfloat16 g_q_hi[MROWS*NH*DH],  g_q_lo[MROWS*NH*DH];  // [bh][n][d] (q pre-scaled)
__device__ __nv_bfloat16 g_k_hi[MROWS*NH*DH],  g_k_lo[MROWS*NH*DH];  // [bh][n][d]
__device__ __nv_bfloat16 g_v_hi[MROWS*NH*DH],  g_v_lo[MROWS*NH*DH];  // [bh][d][n] (transposed)
__device__ __nv_bfloat16 g_att_hi[MROWS*DM],   g_att_lo[MROWS*DM];   // [4096][1024]

__device__ __forceinline__ void ldsm4(uint32_t a, uint32_t& r0, uint32_t& r1, uint32_t& r2, uint32_t& r3) {
    asm volatile("ldmatrix.sync.aligned.m8n8.x4.shared.b16 {%0,%1,%2,%3}, [%4];\n"
                 : "=r"(r0), "=r"(r1), "=r"(r2), "=r"(r3) : "r"(a));
}
__device__ __forceinline__ void mma16816(float* c, const uint32_t* a, uint32_t b0, uint32_t b1) {
    asm volatile("mma.sync.aligned.m16n8k16.row.col.f32.bf16.bf16.f32 "
                 "{%0,%1,%2,%3}, {%4,%5,%6,%7}, {%8,%9}, {%0,%1,%2,%3};\n"
                 : "+f"(c[0]), "+f"(c[1]), "+f"(c[2]), "+f"(c[3])
                 : "r"(a[0]), "r"(a[1]), "r"(a[2]), "r"(a[3]), "r"(b0), "r"(b1));
}
__device__ __forceinline__ void split2(float a, float b, uint32_t& hi, uint32_t& lo) {
    __nv_bfloat16 ha = __float2bfloat16_rn(a), hb = __float2bfloat16_rn(b);
    __nv_bfloat162 h2 = __halves2bfloat162(ha, hb);
    __nv_bfloat162 l2 = __halves2bfloat162(__float2bfloat16_rn(a - __bfloat162float(ha)),
                                           __float2bfloat16_rn(b - __bfloat162float(hb)));
    hi = *(uint32_t*)&h2; lo = *(uint32_t*)&l2;
}

__global__ void split_x_kernel(const float* __restrict__ src) {
    int i = blockIdx.x * 256 + threadIdx.x;
    float v = src[i];
    __nv_bfloat16 h = __float2bfloat16_rn(v);
    g_x_hi[i] = h; g_x_lo[i] = __float2bfloat16_rn(v - __bfloat162float(h));
}
// transpose [1024][N] -> [N][1024] + split. mode 0 = w_qkv, 1 = w_proj
__global__ void split_wt_kernel(const float* __restrict__ src, int N, int mode) {
    __shared__ float t[32][33];
    int n0 = blockIdx.x * 32, k0 = blockIdx.y * 32;
    int tx = threadIdx.x & 31, ty0 = threadIdx.x >> 5;
    for (int ty = ty0; ty < 32; ty += 8) t[ty][tx] = src[(size_t)(k0+ty)*N + n0 + tx];
    __syncthreads();
    __nv_bfloat16* dh = mode ? g_wp_hi : g_wqkv_hi;
    __nv_bfloat16* dl = mode ? g_wp_lo : g_wqkv_lo;
    for (int ty = ty0; ty < 32; ty += 8) {
        float v = t[tx][ty];
        __nv_bfloat16 h = __float2bfloat16_rn(v);
        size_t o = (size_t)(n0+ty)*1024 + k0 + tx;
        dh[o] = h; dl[o] = __float2bfloat16_rn(v - __bfloat162float(h));
    }
}

// ================= tensor-core split GEMM: C[4096 x N] = A @ Bt^T ============
// block 128m x 128n, 8 warps (2m x 4n), warp 64x32, BK=16, double-buffered.
__global__ __launch_bounds__(256) void mma_gemm(float* __restrict__ Cout, int mode)
{
    constexpr int K = 1024;
    __shared__ __align__(16) __nv_bfloat16 sm[2][4][128*24];   // Ahi,Alo,Bhi,Blo

    const __nv_bfloat16* Ahi = mode ? g_att_hi : g_x_hi;
    const __nv_bfloat16* Alo = mode ? g_att_lo : g_x_lo;
    const __nv_bfloat16* Bhi = mode ? g_wp_hi  : g_wqkv_hi;
    const __nv_bfloat16* Blo = mode ? g_wp_lo  : g_wqkv_lo;

    const int m0 = blockIdx.y * 128, n0 = blockIdx.x * 128;
    const int tid = threadIdx.x, w = tid >> 5, lane = tid & 31;
    const int gid = lane >> 2, tig = lane & 3;
    const int wm = (w & 1) * 64, wn = (w >> 1) * 32;

    const int lrow = tid >> 1, lhalf = (tid & 1) * 8;
    const size_t gA = (size_t)(m0 + lrow) * K + lhalf;
    const size_t gB = (size_t)(n0 + lrow) * K + lhalf;
    const int soff = lrow * 24 + lhalf;

    const uint32_t sbase = (uint32_t)__cvta_generic_to_shared(&sm[0][0][0]);
    const int a_r = lane & 15, a_k = (lane >> 4) * 8;
    const int b_r = (lane & 7) + ((lane >> 4) & 1) * 8, b_k = ((lane >> 3) & 1) * 8;

    float acc[4][4][4] = {};
    uint4 va0 = *(const uint4*)(Ahi + gA), va1 = *(const uint4*)(Alo + gA);
    uint4 vb0 = *(const uint4*)(Bhi + gB), vb1 = *(const uint4*)(Blo + gB);
    *(uint4*)&sm[0][0][soff] = va0; *(uint4*)&sm[0][1][soff] = va1;
    *(uint4*)&sm[0][2][soff] = vb0; *(uint4*)&sm[0][3][soff] = vb1;
    __syncthreads();

    int buf = 0;
    for (int k0 = 0; k0 < K; k0 += 16) {
        const bool more = (k0 + 16) < K;
        if (more) {
            va0 = *(const uint4*)(Ahi + gA + k0 + 16); va1 = *(const uint4*)(Alo + gA + k0 + 16);
            vb0 = *(const uint4*)(Bhi + gB + k0 + 16); vb1 = *(const uint4*)(Blo + gB + k0 + 16);
        }
        const uint32_t bo = (uint32_t)buf * (4*128*24*2);
        uint32_t bf[2][2][4];
        #pragma unroll
        for (int g = 0; g < 2; g++)
            #pragma unroll
            for (int p = 0; p < 2; p++) {
                uint32_t ad = sbase + bo + (uint32_t)(2+p)*(128*24*2)
                            + (uint32_t)((wn + g*16 + b_r)*24 + b_k)*2;
                ldsm4(ad, bf[p][g][0], bf[p][g][1], bf[p][g][2], bf[p][g][3]);
            }
        #pragma unroll
        for (int i = 0; i < 4; i++) {
            uint32_t ah[4], al[4];
            uint32_t ad = sbase + bo + (uint32_t)((wm + i*16 + a_r)*24 + a_k)*2;
            ldsm4(ad, ah[0], ah[1], ah[2], ah[3]);
            ldsm4(ad + 128*24*2, al[0], al[1], al[2], al[3]);
            #pragma unroll
            for (int jn = 0; jn < 4; jn++) {
                const int g = jn >> 1, h = (jn & 1) * 2;
                mma16816(acc[i][jn], ah, bf[0][g][h], bf[0][g][h+1]);
                mma16816(acc[i][jn], ah, bf[1][g][h], bf[1][g][h+1]);
                mma16816(acc[i][jn], al, bf[0][g][h], bf[0][g][h+1]);
            }
        }
        if (more) {
            const int nb = buf ^ 1;
            *(uint4*)&sm[nb][0][soff] = va0; *(uint4*)&sm[nb][1][soff] = va1;
            *(uint4*)&sm[nb][2][soff] = vb0; *(uint4*)&sm[nb][3][soff] = vb1;
            __syncthreads();
            buf = nb;
        }
    }

    #pragma unroll
    for (int i = 0; i < 4; i++) {
        const int row0 = m0 + wm + i*16 + gid;
        #pragma unroll
        for (int jn = 0; jn < 4; jn++) {
            const int col = n0 + wn + jn*8 + tig*2;
            if (mode == 1) {
                *(float2*)&Cout[(size_t)row0*1024 + col]     = make_float2(acc[i][jn][0], acc[i][jn][1]);
                *(float2*)&Cout[(size_t)(row0+8)*1024 + col] = make_float2(acc[i][jn][2], acc[i][jn][3]);
            } else {
                #pragma unroll
                for (int r = 0; r < 4; r++) {
                    const int rr = row0 + ((r >= 2) ? 8 : 0), cc = col + (r & 1);
                    float v = acc[i][jn][r];
                    const int which = cc % 3, hd = cc / 3, h = hd >> 6, d = hd & 63;
                    const int bb = rr >> 11, nn = rr & 2047;
                    __nv_bfloat16 h16; size_t o;
                    if (which == 0) {
                        v *= 0.125f;
                        o = ((size_t)(bb*16 + h)*2048 + nn)*64 + d;
                        h16 = __float2bfloat16_rn(v);
                        g_q_hi[o] = h16; g_q_lo[o] = __float2bfloat16_rn(v - __bfloat162float(h16));
                    } else if (which == 1) {
                        o = ((size_t)(bb*16 + h)*2048 + nn)*64 + d;
                        h16 = __float2bfloat16_rn(v);
                        g_k_hi[o] = h16; g_k_lo[o] = __float2bfloat16_rn(v - __bfloat162float(h16));
                    } else {
                        o = ((size_t)(bb*16 + h)*64 + d)*2048 + nn;
                        h16 = __float2bfloat16_rn(v);
                        g_v_hi[o] = h16; g_v_lo[o] = __float2bfloat16_rn(v - __bfloat162float(h16));
                    }
                }
            }
        }
    }
}

// ================= tensor-core causal flash attention ========================
// block 256 thr (8 warps), q-tile 128 (warp w: rows w*16..), k-tile 64.
// smem 64KB dyn: Qhi(8192) Qlo | Khi(4096) Klo | Vhi(4096) Vlo, bf16 elems.
// row layout: 64 cols as 8 cells of 8; off = r*64 + ((c16 ^ (r&7))*8).
__global__ __launch_bounds__(256) void attn_mma()
{
    extern __shared__ __align__(16) __nv_bfloat16 dsm[];
    constexpr int QHI=0, QLO=8192, KHI=16384, KLO=20480, VHI=24576, VLO=28672;

    const int qt = (int)gridDim.x - 1 - (int)blockIdx.x;
    const int bh = blockIdx.y, bb = bh >> 4, hh = bh & 15;
    const size_t base = (size_t)bh * (2048*64);
    const int tid = threadIdx.x, w = tid >> 5, lane = tid & 31;
    const int gid = lane >> 2, tig = lane & 3;
    const uint32_t sbase = (uint32_t)__cvta_generic_to_shared(dsm);
    const int a_r = lane & 15, a_k8 = lane >> 4;
    const int b_r = (lane & 7) + ((lane >> 4) & 1) * 8, b_k8 = (lane >> 3) & 1;

    #pragma unroll
    for (int it = 0; it < 4; it++) {
        const int u = tid + 256*it, r = u >> 3, c16 = u & 7;
        const int so = r*64 + ((c16 ^ (r & 7))*8);
        const size_t go = base + (size_t)(qt*128 + r)*64 + c16*8;
        *(uint4*)&dsm[QHI + so] = *(const uint4*)(g_q_hi + go);
        *(uint4*)&dsm[QLO + so] = *(const uint4*)(g_q_lo + go);
    }

    float s[8][4], o[8][4] = {};
    float mr0 = -1e30f, mr1 = -1e30f, lr0 = 0.f, lr1 = 0.f;
    const int row0g = qt*128 + w*16 + gid, row1g = row0g + 8;
    const int ntiles = 2*qt + 2;

    for (int kt = 0; kt < ntiles; kt++) {
        __syncthreads();
        #pragma unroll
        for (int it = 0; it < 2; it++) {
            const int u = tid + 256*it, r = u >> 3, c16 = u & 7;
            const int so = r*64 + ((c16 ^ (r & 7))*8);
            const size_t gk = base + (size_t)(kt*64 + r)*64 + c16*8;
            const size_t gv = base + (size_t)r*2048 + kt*64 + c16*8;
            *(uint4*)&dsm[KHI + so] = *(const uint4*)(g_k_hi + gk);
            *(uint4*)&dsm[KLO + so] = *(const uint4*)(g_k_lo + gk);
            *(uint4*)&dsm[VHI + so] = *(const uint4*)(g_v_hi + gv);
            *(uint4*)&dsm[VLO + so] = *(const uint4*)(g_v_lo + gv);
        }
        __syncthreads();

        #pragma unroll
        for (int j = 0; j < 8; j++)
            #pragma unroll
            for (int r = 0; r < 4; r++) s[j][r] = 0.f;
        #pragma unroll
        for (int kk = 0; kk < 4; kk++) {
            uint32_t aqh[4], aql[4];
            {
                const int r = w*16 + a_r, c16 = kk*2 + a_k8;
                const int so = r*64 + ((c16 ^ (r & 7))*8);
                ldsm4(sbase + (uint32_t)(QHI + so)*2, aqh[0], aqh[1], aqh[2], aqh[3]);
                ldsm4(sbase + (uint32_t)(QLO + so)*2, aql[0], aql[1], aql[2], aql[3]);
            }
            uint32_t bk[2][4][4];
            #pragma unroll
            for (int g = 0; g < 4; g++) {
                const int r = g*16 + b_r, c16 = kk*2 + b_k8;
                const int so = r*64 + ((c16 ^ (r & 7))*8);
                ldsm4(sbase + (uint32_t)(KHI + so)*2, bk[0][g][0], bk[0][g][1], bk[0][g][2], bk[0][g][3]);
                ldsm4(sbase + (uint32_t)(KLO + so)*2, bk[1][g][0], bk[1][g][1], bk[1][g][2], bk[1][g][3]);
            }
            #pragma unroll
            for (int j8 = 0; j8 < 8; j8++) {
                const int g = j8 >> 1, h = (j8 & 1)*2;
                mma16816(s[j8], aqh, bk[0][g][h], bk[0][g][h+1]);
                mma16816(s[j8], aqh, bk[1][g][h], bk[1][g][h+1]);
                mma16816(s[j8], aql, bk[0][g][h], bk[0][g][h+1]);
            }
        }

        if (kt >= 2*qt) {
            #pragma unroll
            for (int j8 = 0; j8 < 8; j8++) {
                const int c = kt*64 + j8*8 + tig*2;
                if (c > row0g)   s[j8][0] = -1e30f;
                if (c+1 > row0g) s[j8][1] = -1e30f;
                if (c > row1g)   s[j8][2] = -1e30f;
                if (c+1 > row1g) s[j8][3] = -1e30f;
            }
        }

        float mx0 = -1e30f, mx1 = -1e30f;
        #pragma unroll
        for (int j8 = 0; j8 < 8; j8++) {
            mx0 = fmaxf(mx0, fmaxf(s[j8][0], s[j8][1]));
            mx1 = fmaxf(mx1, fmaxf(s[j8][2], s[j8][3]));
        }
        mx0 = fmaxf(mx0, __shfl_xor_sync(~0u, mx0, 1)); mx0 = fmaxf(mx0, __shfl_xor_sync(~0u, mx0, 2));
        mx1 = fmaxf(mx1, __shfl_xor_sync(~0u, mx1, 1)); mx1 = fmaxf(mx1, __shfl_xor_sync(~0u, mx1, 2));
        const float mn0 = fmaxf(mr0, mx0), mn1 = fmaxf(mr1, mx1);
        const float f0 = __expf(mr0 - mn0), f1 = __expf(mr1 - mn1);
        mr0 = mn0; mr1 = mn1;
        float s0 = 0.f, s1 = 0.f;
        #pragma unroll
        for (int j8 = 0; j8 < 8; j8++) {
            s[j8][0] = __expf(s[j8][0] - mn0); s[j8][1] = __expf(s[j8][1] - mn0);
            s[j8][2] = __expf(s[j8][2] - mn1); s[j8][3] = __expf(s[j8][3] - mn1);
            s0 += s[j8][0] + s[j8][1]; s1 += s[j8][2] + s[j8][3];
        }
        s0 += __shfl_xor_sync(~0u, s0, 1); s0 += __shfl_xor_sync(~0u, s0, 2);
        s1 += __shfl_xor_sync(~0u, s1, 1); s1 += __shfl_xor_sync(~0u, s1, 2);
        lr0 = lr0*f0 + s0; lr1 = lr1*f1 + s1;
        #pragma unroll
        for (int j8 = 0; j8 < 8; j8++) {
            o[j8][0] *= f0; o[j8][1] *= f0; o[j8][2] *= f1; o[j8][3] *= f1;
        }

        #pragma unroll
        for (int kk = 0; kk < 4; kk++) {
            uint32_t aph[4], apl[4];
            split2(s[2*kk][0],   s[2*kk][1],   aph[0], apl[0]);
            split2(s[2*kk][2],   s[2*kk][3],   aph[1], apl[1]);
            split2(s[2*kk+1][0], s[2*kk+1][1], aph[2], apl[2]);
            split2(s[2*kk+1][2], s[2*kk+1][3], aph[3], apl[3]);
            uint32_t bv[2][4][4];
            #pragma unroll
            for (int g = 0; g < 4; g++) {
                const int r = g*16 + b_r, c16 = kk*2 + b_k8;
                const int so = r*64 + ((c16 ^ (r & 7))*8);
                ldsm4(sbase + (uint32_t)(VHI + so)*2, bv[0][g][0], bv[0][g][1], bv[0][g][2], bv[0][g][3]);
                ldsm4(sbase + (uint32_t)(VLO + so)*2, bv[1][g][0], bv[1][g][1], bv[1][g][2], bv[1][g][3]);
            }
            #pragma unroll
            for (int j8 = 0; j8 < 8; j8++) {
                const int g = j8 >> 1, h = (j8 & 1)*2;
                mma16816(o[j8], aph, bv[0][g][h], bv[0][g][h+1]);
                mma16816(o[j8], aph, bv[1][g][h], bv[1][g][h+1]);
                mma16816(o[j8], apl, bv[0][g][h], bv[0][g][h+1]);
            }
        }
    }

    const float i0 = 1.f / lr0, i1 = 1.f / lr1;
    #pragma unroll
    for (int j8 = 0; j8 < 8; j8++) {
        const int col = hh*64 + j8*8 + tig*2;
        uint32_t hi, lo;
        size_t ob = ((size_t)bb*2048 + row0g) * DM + col;
        split2(o[j8][0]*i0, o[j8][1]*i0, hi, lo);
        *(uint32_t*)&g_att_hi[ob] = hi; *(uint32_t*)&g_att_lo[ob] = lo;
        ob = ((size_t)bb*2048 + row1g) * DM + col;
        split2(o[j8][2]*i1, o[j8][3]*i1, hi, lo);
        *(uint32_t*)&g_att_hi[ob] = hi; *(uint32_t*)&g_att_lo[ob] = lo;
    }
}

extern "C" void kernel_launch(void* const* d_in, const int* in_sizes, int n_in,
                              void* d_out, int out_size)
{
    (void)in_sizes; (void)n_in; (void)out_size;
    const float* x      = (const float*)d_in[0];
    const float* w_qkv  = (const float*)d_in[1];
    const float* w_proj = (const float*)d_in[2];
    float* out = (float*)d_out;

    static bool attr_done = false;
    if (!attr_done) {
        cudaFuncSetAttribute(attn_mma, cudaFuncAttributeMaxDynamicSharedMemorySize, 65536);
        attr_done = true;
    }

    split_x_kernel<<<MROWS*DM/256, 256>>>(x);
    split_wt_kernel<<<dim3(96, 32), 256>>>(w_qkv, 3*DM, 0);
    split_wt_kernel<<<dim3(32, 32), 256>>>(w_proj, DM, 1);
    mma_gemm<<<dim3(24, 32), 256>>>(nullptr, 0);
    attn_mma<<<dim3(16, 32), 256, 65536>>>();
    mma_gemm<<<dim3(8, 32), 256>>>(out, 1);
}

// round 6
// speedup vs baseline: 2.0913x; 1.1833x over previous
#include <cuda_runtime.h>
#include <cuda_bf16.h>
#include <cstdint>

constexpr int BATCH = 2, NSEQ = 2048, DM = 1024, NH = 16, DH = 64;
constexpr int MROWS = BATCH * NSEQ;

__device__ __align__(16) __nv_bfloat16 g_x_hi[MROWS*DM],     g_x_lo[MROWS*DM];
__device__ __align__(16) __nv_bfloat16 g_wqkv_hi[3*DM*DM],   g_wqkv_lo[3*DM*DM];   // [3072][1024] (transposed)
__device__ __align__(16) __nv_bfloat16 g_wp_hi[DM*DM],       g_wp_lo[DM*DM];       // [1024][1024] (transposed)
__device__ __align__(16) __nv_bfloat16 g_q_hi[MROWS*NH*DH],  g_q_lo[MROWS*NH*DH];  // [bh][n][d] (q pre-scaled)
__device__ __align__(16) __nv_bfloat16 g_k_hi[MROWS*NH*DH],  g_k_lo[MROWS*NH*DH];  // [bh][n][d]
__device__ __align__(16) __nv_bfloat16 g_v_hi[MROWS*NH*DH],  g_v_lo[MROWS*NH*DH];  // [bh][d][n] (transposed)
__device__ __align__(16) __nv_bfloat16 g_att_hi[MROWS*DM],   g_att_lo[MROWS*DM];   // [4096][1024]

// ---------------- helpers ----------------
__device__ __forceinline__ void ldsm4(uint32_t a, uint32_t& r0, uint32_t& r1, uint32_t& r2, uint32_t& r3) {
    asm volatile("ldmatrix.sync.aligned.m8n8.x4.shared.b16 {%0,%1,%2,%3}, [%4];\n"
                 : "=r"(r0), "=r"(r1), "=r"(r2), "=r"(r3) : "r"(a));
}
__device__ __forceinline__ void mma16816(float* c, const uint32_t* a, uint32_t b0, uint32_t b1) {
    asm volatile("mma.sync.aligned.m16n8k16.row.col.f32.bf16.bf16.f32 "
                 "{%0,%1,%2,%3}, {%4,%5,%6,%7}, {%8,%9}, {%0,%1,%2,%3};\n"
                 : "+f"(c[0]), "+f"(c[1]), "+f"(c[2]), "+f"(c[3])
                 : "r"(a[0]), "r"(a[1]), "r"(a[2]), "r"(a[3]), "r"(b0), "r"(b1));
}
__device__ __forceinline__ void split2(float a, float b, uint32_t& hi, uint32_t& lo) {
    __nv_bfloat16 ha = __float2bfloat16_rn(a), hb = __float2bfloat16_rn(b);
    __nv_bfloat162 h2 = __halves2bfloat162(ha, hb);
    __nv_bfloat162 l2 = __halves2bfloat162(__float2bfloat16_rn(a - __bfloat162float(ha)),
                                           __float2bfloat16_rn(b - __bfloat162float(hb)));
    hi = *(uint32_t*)&h2; lo = *(uint32_t*)&l2;
}
__device__ __forceinline__ void cp_async16(uint32_t dst, const void* src) {
    asm volatile("cp.async.cg.shared.global [%0], [%1], 16;\n" :: "r"(dst), "l"(src) : "memory");
}
__device__ __forceinline__ void cp_commit() { asm volatile("cp.async.commit_group;\n" ::: "memory"); }
template<int N> __device__ __forceinline__ void cp_wait() {
    asm volatile("cp.async.wait_group %0;\n" :: "n"(N) : "memory");
}

// ---------------- split prep kernels ----------------
__global__ void split_x_kernel(const float* __restrict__ src) {
    int i = blockIdx.x * 256 + threadIdx.x;
    float v = src[i];
    __nv_bfloat16 h = __float2bfloat16_rn(v);
    g_x_hi[i] = h; g_x_lo[i] = __float2bfloat16_rn(v - __bfloat162float(h));
}
__global__ void split_wt_kernel(const float* __restrict__ src, int N, int mode) {
    __shared__ float t[32][33];
    int n0 = blockIdx.x * 32, k0 = blockIdx.y * 32;
    int tx = threadIdx.x & 31, ty0 = threadIdx.x >> 5;
    for (int ty = ty0; ty < 32; ty += 8) t[ty][tx] = src[(size_t)(k0+ty)*N + n0 + tx];
    __syncthreads();
    __nv_bfloat16* dh = mode ? g_wp_hi : g_wqkv_hi;
    __nv_bfloat16* dl = mode ? g_wp_lo : g_wqkv_lo;
    for (int ty = ty0; ty < 32; ty += 8) {
        float v = t[tx][ty];
        __nv_bfloat16 h = __float2bfloat16_rn(v);
        size_t o = (size_t)(n0+ty)*1024 + k0 + tx;
        dh[o] = h; dl[o] = __float2bfloat16_rn(v - __bfloat162float(h));
    }
}

// =====================================================================
// Legacy-HMMA split GEMM, cp.async 3-stage ring, 2 CTAs/SM.
// C[4096 x N] = A @ Bt^T, block 128m x 128n, 8 warps (2m x 4n), BK=16.
// smem/stage: 4 planes (Ahi,Alo,Bhi,Blo) x 128 rows x 24 bf16 (16 data + 8 pad).
// mode 0: qkv (scatter split q/k/v).  mode 1: proj (fp32 out).
// =====================================================================
constexpr uint32_t STAGE_BYTES = 4 * 128 * 24 * 2;   // 24576
constexpr int GEMM_SMEM = 3 * (int)STAGE_BYTES;       // 73728

__global__ __launch_bounds__(256, 2) void mma_gemm(float* __restrict__ Cout, int mode)
{
    extern __shared__ __align__(16) char dynsm[];
    const uint32_t sbase = (uint32_t)__cvta_generic_to_shared(dynsm);

    const __nv_bfloat16* Ahi = mode ? g_att_hi : g_x_hi;
    const __nv_bfloat16* Alo = mode ? g_att_lo : g_x_lo;
    const __nv_bfloat16* Bhi = mode ? g_wp_hi  : g_wqkv_hi;
    const __nv_bfloat16* Blo = mode ? g_wp_lo  : g_wqkv_lo;

    const int m0 = blockIdx.y * 128, n0 = blockIdx.x * 128;
    const int tid = threadIdx.x, w = tid >> 5, lane = tid & 31;
    const int gid = lane >> 2, tig = lane & 3;
    const int wm = (w & 1) * 64, wn = (w >> 1) * 32;

    const __nv_bfloat16* planes[4] = { Ahi + (size_t)m0 * 1024, Alo + (size_t)m0 * 1024,
                                       Bhi + (size_t)n0 * 1024, Blo + (size_t)n0 * 1024 };

    // cp.async per stage: 1024 16B-chunks (4 planes x 128 rows x 2 halves), 4/thread
    const int c_plane = tid >> 6;            // 0..3
    const int c_row0  = (tid >> 1) & 31;     // 0..31 (x4 over i)
    const int c_half  = tid & 1;
    auto issue_stage = [&](int s) {
        const uint32_t sbuf = sbase + (uint32_t)(s % 3) * STAGE_BYTES;
        #pragma unroll
        for (int i = 0; i < 4; i++) {
            const int row = c_row0 + 32 * i;
            cp_async16(sbuf + c_plane * 6144u + row * 48u + c_half * 16u,
                       planes[c_plane] + (size_t)row * 1024 + s * 16 + c_half * 8);
        }
        cp_commit();
    };

    const int a_r = lane & 15, a_k = (lane >> 4) * 8;
    const int b_r = (lane & 7) + ((lane >> 4) & 1) * 8, b_k = ((lane >> 3) & 1) * 8;

    issue_stage(0);
    issue_stage(1);

    float acc[4][4][4] = {};

    for (int s = 0; s < 64; s++) {
        cp_wait<1>();
        __syncthreads();
        const uint32_t bo = (uint32_t)(s % 3) * STAGE_BYTES;
        uint32_t bf[2][2][4];
        #pragma unroll
        for (int g = 0; g < 2; g++)
            #pragma unroll
            for (int p = 0; p < 2; p++) {
                const uint32_t ad = sbase + bo + (uint32_t)(2 + p) * 6144u
                                  + (uint32_t)((wn + g * 16 + b_r) * 24 + b_k) * 2;
                ldsm4(ad, bf[p][g][0], bf[p][g][1], bf[p][g][2], bf[p][g][3]);
            }
        #pragma unroll
        for (int i = 0; i < 4; i++) {
            uint32_t ah[4], al[4];
            const uint32_t ad = sbase + bo + (uint32_t)((wm + i * 16 + a_r) * 24 + a_k) * 2;
            ldsm4(ad, ah[0], ah[1], ah[2], ah[3]);
            ldsm4(ad + 6144u, al[0], al[1], al[2], al[3]);
            #pragma unroll
            for (int jn = 0; jn < 4; jn++) {
                const int g = jn >> 1, h = (jn & 1) * 2;
                mma16816(acc[i][jn], ah, bf[0][g][h], bf[0][g][h+1]);
                mma16816(acc[i][jn], ah, bf[1][g][h], bf[1][g][h+1]);
                mma16816(acc[i][jn], al, bf[0][g][h], bf[0][g][h+1]);
            }
        }
        if (s + 2 < 64) issue_stage(s + 2);
        else cp_commit();
    }

    // ---------------- epilogue ----------------
    #pragma unroll
    for (int i = 0; i < 4; i++) {
        const int row0 = m0 + wm + i*16 + gid;
        #pragma unroll
        for (int jn = 0; jn < 4; jn++) {
            const int col = n0 + wn + jn*8 + tig*2;
            if (mode == 1) {
                *(float2*)&Cout[(size_t)row0*1024 + col]     = make_float2(acc[i][jn][0], acc[i][jn][1]);
                *(float2*)&Cout[(size_t)(row0+8)*1024 + col] = make_float2(acc[i][jn][2], acc[i][jn][3]);
            } else {
                #pragma unroll
                for (int r = 0; r < 4; r++) {
                    const int rr = row0 + ((r >= 2) ? 8 : 0), cc = col + (r & 1);
                    float v = acc[i][jn][r];
                    const int which = cc % 3, hd = cc / 3, h = hd >> 6, d = hd & 63;
                    const int bb = rr >> 11, nn = rr & 2047;
                    __nv_bfloat16 h16; size_t o;
                    if (which == 0) {
                        v *= 0.125f;
                        o = ((size_t)(bb*16 + h)*2048 + nn)*64 + d;
                        h16 = __float2bfloat16_rn(v);
                        g_q_hi[o] = h16; g_q_lo[o] = __float2bfloat16_rn(v - __bfloat162float(h16));
                    } else if (which == 1) {
                        o = ((size_t)(bb*16 + h)*2048 + nn)*64 + d;
                        h16 = __float2bfloat16_rn(v);
                        g_k_hi[o] = h16; g_k_lo[o] = __float2bfloat16_rn(v - __bfloat162float(h16));
                    } else {
                        o = ((size_t)(bb*16 + h)*64 + d)*2048 + nn;
                        h16 = __float2bfloat16_rn(v);
                        g_v_hi[o] = h16; g_v_lo[o] = __float2bfloat16_rn(v - __bfloat162float(h16));
                    }
                }
            }
        }
    }
}

// ================= tensor-core causal flash attention (unchanged from R4) =====
__global__ __launch_bounds__(256) void attn_mma()
{
    extern __shared__ __align__(16) __nv_bfloat16 dsm[];
    constexpr int QHI=0, QLO=8192, KHI=16384, KLO=20480, VHI=24576, VLO=28672;

    const int qt = (int)gridDim.x - 1 - (int)blockIdx.x;
    const int bh = blockIdx.y, bb = bh >> 4, hh = bh & 15;
    const size_t base = (size_t)bh * (2048*64);
    const int tid = threadIdx.x, w = tid >> 5, lane = tid & 31;
    const int gid = lane >> 2, tig = lane & 3;
    const uint32_t sbase = (uint32_t)__cvta_generic_to_shared(dsm);
    const int a_r = lane & 15, a_k8 = lane >> 4;
    const int b_r = (lane & 7) + ((lane >> 4) & 1) * 8, b_k8 = (lane >> 3) & 1;

    #pragma unroll
    for (int it = 0; it < 4; it++) {
        const int u = tid + 256*it, r = u >> 3, c16 = u & 7;
        const int so = r*64 + ((c16 ^ (r & 7))*8);
        const size_t go = base + (size_t)(qt*128 + r)*64 + c16*8;
        *(uint4*)&dsm[QHI + so] = *(const uint4*)(g_q_hi + go);
        *(uint4*)&dsm[QLO + so] = *(const uint4*)(g_q_lo + go);
    }

    float s[8][4], o[8][4] = {};
    float mr0 = -1e30f, mr1 = -1e30f, lr0 = 0.f, lr1 = 0.f;
    const int row0g = qt*128 + w*16 + gid, row1g = row0g + 8;
    const int ntiles = 2*qt + 2;

    for (int kt = 0; kt < ntiles; kt++) {
        __syncthreads();
        #pragma unroll
        for (int it = 0; it < 2; it++) {
            const int u = tid + 256*it, r = u >> 3, c16 = u & 7;
            const int so = r*64 + ((c16 ^ (r & 7))*8);
            const size_t gk = base + (size_t)(kt*64 + r)*64 + c16*8;
            const size_t gv = base + (size_t)r*2048 + kt*64 + c16*8;
            *(uint4*)&dsm[KHI + so] = *(const uint4*)(g_k_hi + gk);
            *(uint4*)&dsm[KLO + so] = *(const uint4*)(g_k_lo + gk);
            *(uint4*)&dsm[VHI + so] = *(const uint4*)(g_v_hi + gv);
            *(uint4*)&dsm[VLO + so] = *(const uint4*)(g_v_lo + gv);
        }
        __syncthreads();

        #pragma unroll
        for (int j = 0; j < 8; j++)
            #pragma unroll
            for (int r = 0; r < 4; r++) s[j][r] = 0.f;
        #pragma unroll
        for (int kk = 0; kk < 4; kk++) {
            uint32_t aqh[4], aql[4];
            {
                const int r = w*16 + a_r, c16 = kk*2 + a_k8;
                const int so = r*64 + ((c16 ^ (r & 7))*8);
                ldsm4(sbase + (uint32_t)(QHI + so)*2, aqh[0], aqh[1], aqh[2], aqh[3]);
                ldsm4(sbase + (uint32_t)(QLO + so)*2, aql[0], aql[1], aql[2], aql[3]);
            }
            uint32_t bk[2][4][4];
            #pragma unroll
            for (int g = 0; g < 4; g++) {
                const int r = g*16 + b_r, c16 = kk*2 + b_k8;
                const int so = r*64 + ((c16 ^ (r & 7))*8);
                ldsm4(sbase + (uint32_t)(KHI + so)*2, bk[0][g][0], bk[0][g][1], bk[0][g][2], bk[0][g][3]);
                ldsm4(sbase + (uint32_t)(KLO + so)*2, bk[1][g][0], bk[1][g][1], bk[1][g][2], bk[1][g][3]);
            }
            #pragma unroll
            for (int j8 = 0; j8 < 8; j8++) {
                const int g = j8 >> 1, h = (j8 & 1)*2;
                mma16816(s[j8], aqh, bk[0][g][h], bk[0][g][h+1]);
                mma16816(s[j8], aqh, bk[1][g][h], bk[1][g][h+1]);
                mma16816(s[j8], aql, bk[0][g][h], bk[0][g][h+1]);
            }
        }

        if (kt >= 2*qt) {
            #pragma unroll
            for (int j8 = 0; j8 < 8; j8++) {
                const int c = kt*64 + j8*8 + tig*2;
                if (c > row0g)   s[j8][0] = -1e30f;
                if (c+1 > row0g) s[j8][1] = -1e30f;
                if (c > row1g)   s[j8][2] = -1e30f;
                if (c+1 > row1g) s[j8][3] = -1e30f;
            }
        }

        float mx0 = -1e30f, mx1 = -1e30f;
        #pragma unroll
        for (int j8 = 0; j8 < 8; j8++) {
            mx0 = fmaxf(mx0, fmaxf(s[j8][0], s[j8][1]));
            mx1 = fmaxf(mx1, fmaxf(s[j8][2], s[j8][3]));
        }
        mx0 = fmaxf(mx0, __shfl_xor_sync(~0u, mx0, 1)); mx0 = fmaxf(mx0, __shfl_xor_sync(~0u, mx0, 2));
        mx1 = fmaxf(mx1, __shfl_xor_sync(~0u, mx1, 1)); mx1 = fmaxf(mx1, __shfl_xor_sync(~0u, mx1, 2));
        const float mn0 = fmaxf(mr0, mx0), mn1 = fmaxf(mr1, mx1);
        const float f0 = __expf(mr0 - mn0), f1 = __expf(mr1 - mn1);
        mr0 = mn0; mr1 = mn1;
        float s0 = 0.f, s1 = 0.f;
        #pragma unroll
        for (int j8 = 0; j8 < 8; j8++) {
            s[j8][0] = __expf(s[j8][0] - mn0); s[j8][1] = __expf(s[j8][1] - mn0);
            s[j8][2] = __expf(s[j8][2] - mn1); s[j8][3] = __expf(s[j8][3] - mn1);
            s0 += s[j8][0] + s[j8][1]; s1 += s[j8][2] + s[j8][3];
        }
        s0 += __shfl_xor_sync(~0u, s0, 1); s0 += __shfl_xor_sync(~0u, s0, 2);
        s1 += __shfl_xor_sync(~0u, s1, 1); s1 += __shfl_xor_sync(~0u, s1, 2);
        lr0 = lr0*f0 + s0; lr1 = lr1*f1 + s1;
        #pragma unroll
        for (int j8 = 0; j8 < 8; j8++) {
            o[j8][0] *= f0; o[j8][1] *= f0; o[j8][2] *= f1; o[j8][3] *= f1;
        }

        #pragma unroll
        for (int kk = 0; kk < 4; kk++) {
            uint32_t aph[4], apl[4];
            split2(s[2*kk][0],   s[2*kk][1],   aph[0], apl[0]);
            split2(s[2*kk][2],   s[2*kk][3],   aph[1], apl[1]);
            split2(s[2*kk+1][0], s[2*kk+1][1], aph[2], apl[2]);
            split2(s[2*kk+1][2], s[2*kk+1][3], aph[3], apl[3]);
            uint32_t bv[2][4][4];
            #pragma unroll
            for (int g = 0; g < 4; g++) {
                const int r = g*16 + b_r, c16 = kk*2 + b_k8;
                const int so = r*64 + ((c16 ^ (r & 7))*8);
                ldsm4(sbase + (uint32_t)(VHI + so)*2, bv[0][g][0], bv[0][g][1], bv[0][g][2], bv[0][g][3]);
                ldsm4(sbase + (uint32_t)(VLO + so)*2, bv[1][g][0], bv[1][g][1], bv[1][g][2], bv[1][g][3]);
            }
            #pragma unroll
            for (int j8 = 0; j8 < 8; j8++) {
                const int g = j8 >> 1, h = (j8 & 1)*2;
                mma16816(o[j8], aph, bv[0][g][h], bv[0][g][h+1]);
                mma16816(o[j8], aph, bv[1][g][h], bv[1][g][h+1]);
                mma16816(o[j8], apl, bv[0][g][h], bv[0][g][h+1]);
            }
        }
    }

    const float i0 = 1.f / lr0, i1 = 1.f / lr1;
    #pragma unroll
    for (int j8 = 0; j8 < 8; j8++) {
        const int col = hh*64 + j8*8 + tig*2;
        uint32_t hi, lo;
        size_t ob = ((size_t)bb*2048 + row0g) * DM + col;
        split2(o[j8][0]*i0, o[j8][1]*i0, hi, lo);
        *(uint32_t*)&g_att_hi[ob] = hi; *(uint32_t*)&g_att_lo[ob] = lo;
        ob = ((size_t)bb*2048 + row1g) * DM + col;
        split2(o[j8][2]*i1, o[j8][3]*i1, hi, lo);
        *(uint32_t*)&g_att_hi[ob] = hi; *(uint32_t*)&g_att_lo[ob] = lo;
    }
}

extern "C" void kernel_launch(void* const* d_in, const int* in_sizes, int n_in,
                              void* d_out, int out_size)
{
    (void)in_sizes; (void)n_in; (void)out_size;
    const float* x      = (const float*)d_in[0];
    const float* w_qkv  = (const float*)d_in[1];
    const float* w_proj = (const float*)d_in[2];
    float* out = (float*)d_out;

    static bool attr_done = false;
    if (!attr_done) {
        cudaFuncSetAttribute(attn_mma, cudaFuncAttributeMaxDynamicSharedMemorySize, 65536);
        cudaFuncSetAttribute(mma_gemm, cudaFuncAttributeMaxDynamicSharedMemorySize, GEMM_SMEM);
        attr_done = true;
    }

    split_x_kernel<<<MROWS*DM/256, 256>>>(x);
    split_wt_kernel<<<dim3(96, 32), 256>>>(w_qkv, 3*DM, 0);
    split_wt_kernel<<<dim3(32, 32), 256>>>(w_proj, DM, 1);
    mma_gemm<<<dim3(24, 32), 256, GEMM_SMEM>>>(nullptr, 0);
    attn_mma<<<dim3(16, 32), 256, 65536>>>();
    mma_gemm<<<dim3(8, 32), 256, GEMM_SMEM>>>(out, 1);
}

// round 7
// speedup vs baseline: 2.1342x; 1.0205x over previous
#include <cuda_runtime.h>
#include <cuda_bf16.h>
#include <cstdint>

constexpr int BATCH = 2, NSEQ = 2048, DM = 1024, NH = 16, DH = 64;
constexpr int MROWS = BATCH * NSEQ;

__device__ __align__(16) __nv_bfloat16 g_x_hi[MROWS*DM],     g_x_lo[MROWS*DM];
__device__ __align__(16) __nv_bfloat16 g_wqkv_hi[3*DM*DM],   g_wqkv_lo[3*DM*DM];   // [3072][1024] (transposed)
__device__ __align__(16) __nv_bfloat16 g_wp_hi[DM*DM],       g_wp_lo[DM*DM];       // [1024][1024] (transposed)
__device__ __align__(16) __nv_bfloat16 g_q_hi[MROWS*NH*DH],  g_q_lo[MROWS*NH*DH];  // [bh][n][d] (q pre-scaled)
__device__ __align__(16) __nv_bfloat16 g_k_hi[MROWS*NH*DH],  g_k_lo[MROWS*NH*DH];  // [bh][n][d]
__device__ __align__(16) __nv_bfloat16 g_v_hi[MROWS*NH*DH],  g_v_lo[MROWS*NH*DH];  // [bh][d][n] (transposed)
__device__ __align__(16) __nv_bfloat16 g_att_hi[MROWS*DM],   g_att_lo[MROWS*DM];   // [4096][1024]

// ---------------- helpers ----------------
__device__ __forceinline__ void ldsm4(uint32_t a, uint32_t& r0, uint32_t& r1, uint32_t& r2, uint32_t& r3) {
    asm volatile("ldmatrix.sync.aligned.m8n8.x4.shared.b16 {%0,%1,%2,%3}, [%4];\n"
                 : "=r"(r0), "=r"(r1), "=r"(r2), "=r"(r3) : "r"(a));
}
__device__ __forceinline__ void mma16816(float* c, const uint32_t* a, uint32_t b0, uint32_t b1) {
    asm volatile("mma.sync.aligned.m16n8k16.row.col.f32.bf16.bf16.f32 "
                 "{%0,%1,%2,%3}, {%4,%5,%6,%7}, {%8,%9}, {%0,%1,%2,%3};\n"
                 : "+f"(c[0]), "+f"(c[1]), "+f"(c[2]), "+f"(c[3])
                 : "r"(a[0]), "r"(a[1]), "r"(a[2]), "r"(a[3]), "r"(b0), "r"(b1));
}
__device__ __forceinline__ void split2(float a, float b, uint32_t& hi, uint32_t& lo) {
    __nv_bfloat16 ha = __float2bfloat16_rn(a), hb = __float2bfloat16_rn(b);
    __nv_bfloat162 h2 = __halves2bfloat162(ha, hb);
    __nv_bfloat162 l2 = __halves2bfloat162(__float2bfloat16_rn(a - __bfloat162float(ha)),
                                           __float2bfloat16_rn(b - __bfloat162float(hb)));
    hi = *(uint32_t*)&h2; lo = *(uint32_t*)&l2;
}
__device__ __forceinline__ void cp_async16(uint32_t dst, const void* src) {
    asm volatile("cp.async.cg.shared.global [%0], [%1], 16;\n" :: "r"(dst), "l"(src) : "memory");
}
__device__ __forceinline__ void cp_commit() { asm volatile("cp.async.commit_group;\n" ::: "memory"); }
template<int N> __device__ __forceinline__ void cp_wait() {
    asm volatile("cp.async.wait_group %0;\n" :: "n"(N) : "memory");
}

// ---------------- split prep kernels ----------------
__global__ void split_x_kernel(const float* __restrict__ src) {
    int i = blockIdx.x * 256 + threadIdx.x;
    float v = src[i];
    __nv_bfloat16 h = __float2bfloat16_rn(v);
    g_x_hi[i] = h; g_x_lo[i] = __float2bfloat16_rn(v - __bfloat162float(h));
}
__global__ void split_wt_kernel(const float* __restrict__ src, int N, int mode) {
    __shared__ float t[32][33];
    int n0 = blockIdx.x * 32, k0 = blockIdx.y * 32;
    int tx = threadIdx.x & 31, ty0 = threadIdx.x >> 5;
    for (int ty = ty0; ty < 32; ty += 8) t[ty][tx] = src[(size_t)(k0+ty)*N + n0 + tx];
    __syncthreads();
    __nv_bfloat16* dh = mode ? g_wp_hi : g_wqkv_hi;
    __nv_bfloat16* dl = mode ? g_wp_lo : g_wqkv_lo;
    for (int ty = ty0; ty < 32; ty += 8) {
        float v = t[tx][ty];
        __nv_bfloat16 h = __float2bfloat16_rn(v);
        size_t o = (size_t)(n0+ty)*1024 + k0 + tx;
        dh[o] = h; dl[o] = __float2bfloat16_rn(v - __bfloat162float(h));
    }
}

// =====================================================================
// Legacy-HMMA split GEMM v2: swizzled smem (32B rows), 4-stage ring,
// A-fragment double buffering. 128m x 128n CTA tile, 8 warps (2m x 4n).
// smem/stage: 4 planes (Ahi,Alo,Bhi,Blo) x 128 rows x 16 bf16 = 16KB.
// mode 0: qkv (scatter split q/k/v).  mode 1: proj (fp32 out).
// =====================================================================
constexpr uint32_t STAGE_BYTES = 4 * 128 * 32;   // 16384
constexpr int GEMM_SMEM = 4 * (int)STAGE_BYTES;  // 65536

__global__ __launch_bounds__(256, 2) void mma_gemm(float* __restrict__ Cout, int mode)
{
    extern __shared__ __align__(16) char dynsm[];
    const uint32_t sbase = (uint32_t)__cvta_generic_to_shared(dynsm);

    const __nv_bfloat16* Ahi = mode ? g_att_hi : g_x_hi;
    const __nv_bfloat16* Alo = mode ? g_att_lo : g_x_lo;
    const __nv_bfloat16* Bhi = mode ? g_wp_hi  : g_wqkv_hi;
    const __nv_bfloat16* Blo = mode ? g_wp_lo  : g_wqkv_lo;

    const int m0 = blockIdx.y * 128, n0 = blockIdx.x * 128;
    const int tid = threadIdx.x, w = tid >> 5, lane = tid & 31;
    const int gid = lane >> 2, tig = lane & 3;
    const int wm = (w & 1) * 64, wn = (w >> 1) * 32;

    const __nv_bfloat16* planes[4] = { Ahi + (size_t)m0 * 1024, Alo + (size_t)m0 * 1024,
                                       Bhi + (size_t)n0 * 1024, Blo + (size_t)n0 * 1024 };

    // cp.async mapping: 1024 16B-chunks/stage (4 planes x 128 rows x 2 cells), 4/thread
    const int c_plane = tid >> 6;            // 0..3
    const int c_row0  = (tid >> 1) & 31;     // 0..31 (x4 over i)
    const int c_half  = tid & 1;             // 16B cell within the 32B row
    auto issue_stage = [&](int s) {
        const uint32_t sbuf = sbase + (uint32_t)(s & 3) * STAGE_BYTES;
        #pragma unroll
        for (int i = 0; i < 4; i++) {
            const int row = c_row0 + 32 * i;
            const uint32_t cell = (uint32_t)(c_half ^ ((row >> 2) & 1));
            cp_async16(sbuf + c_plane * 4096u + row * 32u + cell * 16u,
                       planes[c_plane] + (size_t)row * 1024 + s * 16 + c_half * 8);
        }
        cp_commit();
    };

    const int a_r = lane & 15, a_k8 = lane >> 4;                       // A frag lane map
    const int b_r = (lane & 7) + ((lane >> 4) & 1) * 8, b_k8 = (lane >> 3) & 1;  // B frag lane map

    issue_stage(0);
    issue_stage(1);
    issue_stage(2);

    float acc[4][4][4] = {};

    for (int s = 0; s < 64; s++) {
        cp_wait<2>();
        __syncthreads();
        if (s + 3 < 64) issue_stage(s + 3);
        else cp_commit();

        const uint32_t bo = sbase + (uint32_t)(s & 3) * STAGE_BYTES;

        // B fragments (2 n-groups x 2 planes)
        uint32_t bf[2][2][4];
        #pragma unroll
        for (int g = 0; g < 2; g++) {
            const int row = wn + g * 16 + b_r;
            const uint32_t ad = bo + (uint32_t)row * 32u
                              + (uint32_t)((b_k8 ^ ((row >> 2) & 1)) * 16);
            ldsm4(ad + 2u * 4096u, bf[0][g][0], bf[0][g][1], bf[0][g][2], bf[0][g][3]);
            ldsm4(ad + 3u * 4096u, bf[1][g][0], bf[1][g][1], bf[1][g][2], bf[1][g][3]);
        }

        // A fragments: double-buffered across i
        uint32_t ah[2][4], al[2][4];
        auto lda = [&](int i, int b) {
            const int row = wm + i * 16 + a_r;
            const uint32_t ad = bo + (uint32_t)row * 32u
                              + (uint32_t)((a_k8 ^ ((row >> 2) & 1)) * 16);
            ldsm4(ad,          ah[b][0], ah[b][1], ah[b][2], ah[b][3]);
            ldsm4(ad + 4096u,  al[b][0], al[b][1], al[b][2], al[b][3]);
        };
        lda(0, 0);
        #pragma unroll
        for (int i = 0; i < 4; i++) {
            if (i < 3) lda(i + 1, (i + 1) & 1);
            const int cb = i & 1;
            #pragma unroll
            for (int jn = 0; jn < 4; jn++) {
                const int g = jn >> 1, h = (jn & 1) * 2;
                mma16816(acc[i][jn], ah[cb], bf[0][g][h], bf[0][g][h+1]);
                mma16816(acc[i][jn], ah[cb], bf[1][g][h], bf[1][g][h+1]);
                mma16816(acc[i][jn], al[cb], bf[0][g][h], bf[0][g][h+1]);
            }
        }
    }

    // ---------------- epilogue ----------------
    #pragma unroll
    for (int i = 0; i < 4; i++) {
        const int row0 = m0 + wm + i*16 + gid;
        #pragma unroll
        for (int jn = 0; jn < 4; jn++) {
            const int col = n0 + wn + jn*8 + tig*2;
            if (mode == 1) {
                *(float2*)&Cout[(size_t)row0*1024 + col]     = make_float2(acc[i][jn][0], acc[i][jn][1]);
                *(float2*)&Cout[(size_t)(row0+8)*1024 + col] = make_float2(acc[i][jn][2], acc[i][jn][3]);
            } else {
                #pragma unroll
                for (int r = 0; r < 4; r++) {
                    const int rr = row0 + ((r >= 2) ? 8 : 0), cc = col + (r & 1);
                    float v = acc[i][jn][r];
                    const int which = cc % 3, hd = cc / 3, h = hd >> 6, d = hd & 63;
                    const int bb = rr >> 11, nn = rr & 2047;
                    __nv_bfloat16 h16; size_t o;
                    if (which == 0) {
                        v *= 0.125f;
                        o = ((size_t)(bb*16 + h)*2048 + nn)*64 + d;
                        h16 = __float2bfloat16_rn(v);
                        g_q_hi[o] = h16; g_q_lo[o] = __float2bfloat16_rn(v - __bfloat162float(h16));
                    } else if (which == 1) {
                        o = ((size_t)(bb*16 + h)*2048 + nn)*64 + d;
                        h16 = __float2bfloat16_rn(v);
                        g_k_hi[o] = h16; g_k_lo[o] = __float2bfloat16_rn(v - __bfloat162float(h16));
                    } else {
                        o = ((size_t)(bb*16 + h)*64 + d)*2048 + nn;
                        h16 = __float2bfloat16_rn(v);
                        g_v_hi[o] = h16; g_v_lo[o] = __float2bfloat16_rn(v - __bfloat162float(h16));
                    }
                }
            }
        }
    }
}

// ================= tensor-core causal flash attention (unchanged) =====
__global__ __launch_bounds__(256) void attn_mma()
{
    extern __shared__ __align__(16) __nv_bfloat16 dsm[];
    constexpr int QHI=0, QLO=8192, KHI=16384, KLO=20480, VHI=24576, VLO=28672;

    const int qt = (int)gridDim.x - 1 - (int)blockIdx.x;
    const int bh = blockIdx.y, bb = bh >> 4, hh = bh & 15;
    const size_t base = (size_t)bh * (2048*64);
    const int tid = threadIdx.x, w = tid >> 5, lane = tid & 31;
    const int gid = lane >> 2, tig = lane & 3;
    const uint32_t sbase = (uint32_t)__cvta_generic_to_shared(dsm);
    const int a_r = lane & 15, a_k8 = lane >> 4;
    const int b_r = (lane & 7) + ((lane >> 4) & 1) * 8, b_k8 = (lane >> 3) & 1;

    #pragma unroll
    for (int it = 0; it < 4; it++) {
        const int u = tid + 256*it, r = u >> 3, c16 = u & 7;
        const int so = r*64 + ((c16 ^ (r & 7))*8);
        const size_t go = base + (size_t)(qt*128 + r)*64 + c16*8;
        *(uint4*)&dsm[QHI + so] = *(const uint4*)(g_q_hi + go);
        *(uint4*)&dsm[QLO + so] = *(const uint4*)(g_q_lo + go);
    }

    float s[8][4], o[8][4] = {};
    float mr0 = -1e30f, mr1 = -1e30f, lr0 = 0.f, lr1 = 0.f;
    const int row0g = qt*128 + w*16 + gid, row1g = row0g + 8;
    const int ntiles = 2*qt + 2;

    for (int kt = 0; kt < ntiles; kt++) {
        __syncthreads();
        #pragma unroll
        for (int it = 0; it < 2; it++) {
            const int u = tid + 256*it, r = u >> 3, c16 = u & 7;
            const int so = r*64 + ((c16 ^ (r & 7))*8);
            const size_t gk = base + (size_t)(kt*64 + r)*64 + c16*8;
            const size_t gv = base + (size_t)r*2048 + kt*64 + c16*8;
            *(uint4*)&dsm[KHI + so] = *(const uint4*)(g_k_hi + gk);
            *(uint4*)&dsm[KLO + so] = *(const uint4*)(g_k_lo + gk);
            *(uint4*)&dsm[VHI + so] = *(const uint4*)(g_v_hi + gv);
            *(uint4*)&dsm[VLO + so] = *(const uint4*)(g_v_lo + gv);
        }
        __syncthreads();

        #pragma unroll
        for (int j = 0; j < 8; j++)
            #pragma unroll
            for (int r = 0; r < 4; r++) s[j][r] = 0.f;
        #pragma unroll
        for (int kk = 0; kk < 4; kk++) {
            uint32_t aqh[4], aql[4];
            {
                const int r = w*16 + a_r, c16 = kk*2 + a_k8;
                const int so = r*64 + ((c16 ^ (r & 7))*8);
                ldsm4(sbase + (uint32_t)(QHI + so)*2, aqh[0], aqh[1], aqh[2], aqh[3]);
                ldsm4(sbase + (uint32_t)(QLO + so)*2, aql[0], aql[1], aql[2], aql[3]);
            }
            uint32_t bk[2][4][4];
            #pragma unroll
            for (int g = 0; g < 4; g++) {
                const int r = g*16 + b_r, c16 = kk*2 + b_k8;
                const int so = r*64 + ((c16 ^ (r & 7))*8);
                ldsm4(sbase + (uint32_t)(KHI + so)*2, bk[0][g][0], bk[0][g][1], bk[0][g][2], bk[0][g][3]);
                ldsm4(sbase + (uint32_t)(KLO + so)*2, bk[1][g][0], bk[1][g][1], bk[1][g][2], bk[1][g][3]);
            }
            #pragma unroll
            for (int j8 = 0; j8 < 8; j8++) {
                const int g = j8 >> 1, h = (j8 & 1)*2;
                mma16816(s[j8], aqh, bk[0][g][h], bk[0][g][h+1]);
                mma16816(s[j8], aqh, bk[1][g][h], bk[1][g][h+1]);
                mma16816(s[j8], aql, bk[0][g][h], bk[0][g][h+1]);
            }
        }

        if (kt >= 2*qt) {
            #pragma unroll
            for (int j8 = 0; j8 < 8; j8++) {
                const int c = kt*64 + j8*8 + tig*2;
                if (c > row0g)   s[j8][0] = -1e30f;
                if (c+1 > row0g) s[j8][1] = -1e30f;
                if (c > row1g)   s[j8][2] = -1e30f;
                if (c+1 > row1g) s[j8][3] = -1e30f;
            }
        }

        float mx0 = -1e30f, mx1 = -1e30f;
        #pragma unroll
        for (int j8 = 0; j8 < 8; j8++) {
            mx0 = fmaxf(mx0, fmaxf(s[j8][0], s[j8][1]));
            mx1 = fmaxf(mx1, fmaxf(s[j8][2], s[j8][3]));
        }
        mx0 = fmaxf(mx0, __shfl_xor_sync(~0u, mx0, 1)); mx0 = fmaxf(mx0, __shfl_xor_sync(~0u, mx0, 2));
        mx1 = fmaxf(mx1, __shfl_xor_sync(~0u, mx1, 1)); mx1 = fmaxf(mx1, __shfl_xor_sync(~0u, mx1, 2));
        const float mn0 = fmaxf(mr0, mx0), mn1 = fmaxf(mr1, mx1);
        const float f0 = __expf(mr0 - mn0), f1 = __expf(mr1 - mn1);
        mr0 = mn0; mr1 = mn1;
        float s0 = 0.f, s1 = 0.f;
        #pragma unroll
        for (int j8 = 0; j8 < 8; j8++) {
            s[j8][0] = __expf(s[j8][0] - mn0); s[j8][1] = __expf(s[j8][1] - mn0);
            s[j8][2] = __expf(s[j8][2] - mn1); s[j8][3] = __expf(s[j8][3] - mn1);
            s0 += s[j8][0] + s[j8][1]; s1 += s[j8][2] + s[j8][3];
        }
        s0 += __shfl_xor_sync(~0u, s0, 1); s0 += __shfl_xor_sync(~0u, s0, 2);
        s1 += __shfl_xor_sync(~0u, s1, 1); s1 += __shfl_xor_sync(~0u, s1, 2);
        lr0 = lr0*f0 + s0; lr1 = lr1*f1 + s1;
        #pragma unroll
        for (int j8 = 0; j8 < 8; j8++) {
            o[j8][0] *= f0; o[j8][1] *= f0; o[j8][2] *= f1; o[j8][3] *= f1;
        }

        #pragma unroll
        for (int kk = 0; kk < 4; kk++) {
            uint32_t aph[4], apl[4];
            split2(s[2*kk][0],   s[2*kk][1],   aph[0], apl[0]);
            split2(s[2*kk][2],   s[2*kk][3],   aph[1], apl[1]);
            split2(s[2*kk+1][0], s[2*kk+1][1], aph[2], apl[2]);
            split2(s[2*kk+1][2], s[2*kk+1][3], aph[3], apl[3]);
            uint32_t bv[2][4][4];
            #pragma unroll
            for (int g = 0; g < 4; g++) {
                const int r = g*16 + b_r, c16 = kk*2 + b_k8;
                const int so = r*64 + ((c16 ^ (r & 7))*8);
                ldsm4(sbase + (uint32_t)(VHI + so)*2, bv[0][g][0], bv[0][g][1], bv[0][g][2], bv[0][g][3]);
                ldsm4(sbase + (uint32_t)(VLO + so)*2, bv[1][g][0], bv[1][g][1], bv[1][g][2], bv[1][g][3]);
            }
            #pragma unroll
            for (int j8 = 0; j8 < 8; j8++) {
                const int g = j8 >> 1, h = (j8 & 1)*2;
                mma16816(o[j8], aph, bv[0][g][h], bv[0][g][h+1]);
                mma16816(o[j8], aph, bv[1][g][h], bv[1][g][h+1]);
                mma16816(o[j8], apl, bv[0][g][h], bv[0][g][h+1]);
            }
        }
    }

    const float i0 = 1.f / lr0, i1 = 1.f / lr1;
    #pragma unroll
    for (int j8 = 0; j8 < 8; j8++) {
        const int col = hh*64 + j8*8 + tig*2;
        uint32_t hi, lo;
        size_t ob = ((size_t)bb*2048 + row0g) * DM + col;
        split2(o[j8][0]*i0, o[j8][1]*i0, hi, lo);
        *(uint32_t*)&g_att_hi[ob] = hi; *(uint32_t*)&g_att_lo[ob] = lo;
        ob = ((size_t)bb*2048 + row1g) * DM + col;
        split2(o[j8][2]*i1, o[j8][3]*i1, hi, lo);
        *(uint32_t*)&g_att_hi[ob] = hi; *(uint32_t*)&g_att_lo[ob] = lo;
    }
}

extern "C" void kernel_launch(void* const* d_in, const int* in_sizes, int n_in,
                              void* d_out, int out_size)
{
    (void)in_sizes; (void)n_in; (void)out_size;
    const float* x      = (const float*)d_in[0];
    const float* w_qkv  = (const float*)d_in[1];
    const float* w_proj = (const float*)d_in[2];
    float* out = (float*)d_out;

    static bool attr_done = false;
    if (!attr_done) {
        cudaFuncSetAttribute(attn_mma, cudaFuncAttributeMaxDynamicSharedMemorySize, 65536);
        cudaFuncSetAttribute(mma_gemm, cudaFuncAttributeMaxDynamicSharedMemorySize, GEMM_SMEM);
        attr_done = true;
    }

    split_x_kernel<<<MROWS*DM/256, 256>>>(x);
    split_wt_kernel<<<dim3(96, 32), 256>>>(w_qkv, 3*DM, 0);
    split_wt_kernel<<<dim3(32, 32), 256>>>(w_proj, DM, 1);
    mma_gemm<<<dim3(24, 32), 256, GEMM_SMEM>>>(nullptr, 0);
    attn_mma<<<dim3(16, 32), 256, 65536>>>();
    mma_gemm<<<dim3(8, 32), 256, GEMM_SMEM>>>(out, 1);
}

// round 8
// speedup vs baseline: 2.4081x; 1.1283x over previous
#include <cuda_runtime.h>
#include <cuda_bf16.h>
#include <cstdint>

constexpr int BATCH = 2, NSEQ = 2048, DM = 1024, NH = 16, DH = 64;
constexpr int MROWS = BATCH * NSEQ;

__device__ __align__(16) __nv_bfloat16 g_x_hi[MROWS*DM],     g_x_lo[MROWS*DM];
__device__ __align__(16) __nv_bfloat16 g_wqkv_hi[3*DM*DM],   g_wqkv_lo[3*DM*DM];   // [3072][1024] (transposed)
__device__ __align__(16) __nv_bfloat16 g_wp_hi[DM*DM],       g_wp_lo[DM*DM];       // [1024][1024] (transposed)
__device__ __align__(16) __nv_bfloat16 g_q_hi[MROWS*NH*DH],  g_q_lo[MROWS*NH*DH];  // [bh][n][d] (q pre-scaled)
__device__ __align__(16) __nv_bfloat16 g_k_hi[MROWS*NH*DH],  g_k_lo[MROWS*NH*DH];  // [bh][n][d]
__device__ __align__(16) __nv_bfloat16 g_v_hi[MROWS*NH*DH],  g_v_lo[MROWS*NH*DH];  // [bh][d][n] (transposed)
__device__ __align__(16) __nv_bfloat16 g_att_hi[MROWS*DM],   g_att_lo[MROWS*DM];   // [4096][1024]

// ---------------- helpers ----------------
__device__ __forceinline__ void ldsm4(uint32_t a, uint32_t& r0, uint32_t& r1, uint32_t& r2, uint32_t& r3) {
    asm volatile("ldmatrix.sync.aligned.m8n8.x4.shared.b16 {%0,%1,%2,%3}, [%4];\n"
                 : "=r"(r0), "=r"(r1), "=r"(r2), "=r"(r3) : "r"(a));
}
__device__ __forceinline__ void mma16816(float* c, const uint32_t* a, uint32_t b0, uint32_t b1) {
    asm volatile("mma.sync.aligned.m16n8k16.row.col.f32.bf16.bf16.f32 "
                 "{%0,%1,%2,%3}, {%4,%5,%6,%7}, {%8,%9}, {%0,%1,%2,%3};\n"
                 : "+f"(c[0]), "+f"(c[1]), "+f"(c[2]), "+f"(c[3])
                 : "r"(a[0]), "r"(a[1]), "r"(a[2]), "r"(a[3]), "r"(b0), "r"(b1));
}
__device__ __forceinline__ void split2(float a, float b, uint32_t& hi, uint32_t& lo) {
    __nv_bfloat16 ha = __float2bfloat16_rn(a), hb = __float2bfloat16_rn(b);
    __nv_bfloat162 h2 = __halves2bfloat162(ha, hb);
    __nv_bfloat162 l2 = __halves2bfloat162(__float2bfloat16_rn(a - __bfloat162float(ha)),
                                           __float2bfloat16_rn(b - __bfloat162float(hb)));
    hi = *(uint32_t*)&h2; lo = *(uint32_t*)&l2;
}
__device__ __forceinline__ void cp_async16(uint32_t dst, const void* src) {
    asm volatile("cp.async.cg.shared.global [%0], [%1], 16;\n" :: "r"(dst), "l"(src) : "memory");
}
__device__ __forceinline__ void cp_commit() { asm volatile("cp.async.commit_group;\n" ::: "memory"); }
template<int N> __device__ __forceinline__ void cp_wait() {
    asm volatile("cp.async.wait_group %0;\n" :: "n"(N) : "memory");
}

// ---------------- split prep kernels ----------------
__global__ void split_x_kernel(const float* __restrict__ src) {
    int i = blockIdx.x * 256 + threadIdx.x;
    float v = src[i];
    __nv_bfloat16 h = __float2bfloat16_rn(v);
    g_x_hi[i] = h; g_x_lo[i] = __float2bfloat16_rn(v - __bfloat162float(h));
}
__global__ void split_wt_kernel(const float* __restrict__ src, int N, int mode) {
    __shared__ float t[32][33];
    int n0 = blockIdx.x * 32, k0 = blockIdx.y * 32;
    int tx = threadIdx.x & 31, ty0 = threadIdx.x >> 5;
    for (int ty = ty0; ty < 32; ty += 8) t[ty][tx] = src[(size_t)(k0+ty)*N + n0 + tx];
    __syncthreads();
    __nv_bfloat16* dh = mode ? g_wp_hi : g_wqkv_hi;
    __nv_bfloat16* dl = mode ? g_wp_lo : g_wqkv_lo;
    for (int ty = ty0; ty < 32; ty += 8) {
        float v = t[tx][ty];
        __nv_bfloat16 h = __float2bfloat16_rn(v);
        size_t o = (size_t)(n0+ty)*1024 + k0 + tx;
        dh[o] = h; dl[o] = __float2bfloat16_rn(v - __bfloat162float(h));
    }
}

// =====================================================================
// Legacy-HMMA split GEMM v3: BK=32 stages (32KB), 3-stage ring,
// one barrier per stage, swizzled 64B rows. 8 warps (2m x 4n), 2 CTA/SM.
// mode 0: qkv (scatter split q/k/v).  mode 1: proj (fp32 out).
// =====================================================================
constexpr uint32_t G_STAGE = 4u * 128u * 64u;    // 32768 bytes
constexpr int GEMM_SMEM = 3 * (int)G_STAGE;      // 98304

__global__ __launch_bounds__(256, 2) void mma_gemm(float* __restrict__ Cout, int mode)
{
    extern __shared__ __align__(16) char dynsm[];
    const uint32_t sbase = (uint32_t)__cvta_generic_to_shared(dynsm);

    const __nv_bfloat16* Ahi = mode ? g_att_hi : g_x_hi;
    const __nv_bfloat16* Alo = mode ? g_att_lo : g_x_lo;
    const __nv_bfloat16* Bhi = mode ? g_wp_hi  : g_wqkv_hi;
    const __nv_bfloat16* Blo = mode ? g_wp_lo  : g_wqkv_lo;

    const int m0 = blockIdx.y * 128, n0 = blockIdx.x * 128;
    const int tid = threadIdx.x, w = tid >> 5, lane = tid & 31;
    const int gid = lane >> 2, tig = lane & 3;
    const int wm = (w & 1) * 64, wn = (w >> 1) * 32;

    const __nv_bfloat16* planes[4] = { Ahi + (size_t)m0 * 1024, Alo + (size_t)m0 * 1024,
                                       Bhi + (size_t)n0 * 1024, Blo + (size_t)n0 * 1024 };

    // per stage: 4 planes x 128 rows x 4 cells(16B) = 2048 chunks, 8/thread
    auto issue_stage = [&](int s) {
        const uint32_t sbuf = sbase + (uint32_t)(s % 3) * G_STAGE;
        #pragma unroll
        for (int i = 0; i < 8; i++) {
            const int u = tid + 256 * i;
            const int plane = u >> 9, rem = u & 511;
            const int row = rem >> 2, cell = rem & 3;
            const uint32_t csw = (uint32_t)(cell ^ ((row >> 1) & 3));
            cp_async16(sbuf + (uint32_t)plane * 8192u + (uint32_t)row * 64u + csw * 16u,
                       planes[plane] + (size_t)row * 1024 + s * 32 + cell * 8);
        }
        cp_commit();
    };

    const int a_r = lane & 15, a_k8 = lane >> 4;
    const int b_r = (lane & 7) + ((lane >> 4) & 1) * 8, b_k8 = (lane >> 3) & 1;

    issue_stage(0);
    issue_stage(1);

    float acc[4][4][4] = {};

    for (int s = 0; s < 32; s++) {
        cp_wait<1>();
        __syncthreads();
        if (s + 2 < 32) issue_stage(s + 2);
        else cp_commit();

        const uint32_t bo = sbase + (uint32_t)(s % 3) * G_STAGE;

        #pragma unroll
        for (int hk = 0; hk < 2; hk++) {
            // B fragments (2 n-groups x 2 planes)
            uint32_t bf[2][2][4];
            #pragma unroll
            for (int g = 0; g < 2; g++) {
                const int row = wn + g * 16 + b_r;
                const uint32_t csw = (uint32_t)((hk * 2 + b_k8) ^ ((row >> 1) & 3));
                const uint32_t ad = bo + (uint32_t)row * 64u + csw * 16u;
                ldsm4(ad + 2u * 8192u, bf[0][g][0], bf[0][g][1], bf[0][g][2], bf[0][g][3]);
                ldsm4(ad + 3u * 8192u, bf[1][g][0], bf[1][g][1], bf[1][g][2], bf[1][g][3]);
            }
            // A fragments: double-buffered across i
            uint32_t ah[2][4], al[2][4];
            auto lda = [&](int i, int b) {
                const int row = wm + i * 16 + a_r;
                const uint32_t csw = (uint32_t)((hk * 2 + a_k8) ^ ((row >> 1) & 3));
                const uint32_t ad = bo + (uint32_t)row * 64u + csw * 16u;
                ldsm4(ad,         ah[b][0], ah[b][1], ah[b][2], ah[b][3]);
                ldsm4(ad + 8192u, al[b][0], al[b][1], al[b][2], al[b][3]);
            };
            lda(0, 0);
            #pragma unroll
            for (int i = 0; i < 4; i++) {
                if (i < 3) lda(i + 1, (i + 1) & 1);
                const int cb = i & 1;
                #pragma unroll
                for (int jn = 0; jn < 4; jn++) {
                    const int g = jn >> 1, h2 = (jn & 1) * 2;
                    mma16816(acc[i][jn], ah[cb], bf[0][g][h2], bf[0][g][h2+1]);
                    mma16816(acc[i][jn], ah[cb], bf[1][g][h2], bf[1][g][h2+1]);
                    mma16816(acc[i][jn], al[cb], bf[0][g][h2], bf[0][g][h2+1]);
                }
            }
        }
    }

    // ---------------- epilogue ----------------
    #pragma unroll
    for (int i = 0; i < 4; i++) {
        const int row0 = m0 + wm + i*16 + gid;
        #pragma unroll
        for (int jn = 0; jn < 4; jn++) {
            const int col = n0 + wn + jn*8 + tig*2;
            if (mode == 1) {
                *(float2*)&Cout[(size_t)row0*1024 + col]     = make_float2(acc[i][jn][0], acc[i][jn][1]);
                *(float2*)&Cout[(size_t)(row0+8)*1024 + col] = make_float2(acc[i][jn][2], acc[i][jn][3]);
            } else {
                #pragma unroll
                for (int r = 0; r < 4; r++) {
                    const int rr = row0 + ((r >= 2) ? 8 : 0), cc = col + (r & 1);
                    float v = acc[i][jn][r];
                    const int which = cc % 3, hd = cc / 3, h = hd >> 6, d = hd & 63;
                    const int bb = rr >> 11, nn = rr & 2047;
                    __nv_bfloat16 h16; size_t o;
                    if (which == 0) {
                        v *= 0.125f;
                        o = ((size_t)(bb*16 + h)*2048 + nn)*64 + d;
                        h16 = __float2bfloat16_rn(v);
                        g_q_hi[o] = h16; g_q_lo[o] = __float2bfloat16_rn(v - __bfloat162float(h16));
                    } else if (which == 1) {
                        o = ((size_t)(bb*16 + h)*2048 + nn)*64 + d;
                        h16 = __float2bfloat16_rn(v);
                        g_k_hi[o] = h16; g_k_lo[o] = __float2bfloat16_rn(v - __bfloat162float(h16));
                    } else {
                        o = ((size_t)(bb*16 + h)*64 + d)*2048 + nn;
                        h16 = __float2bfloat16_rn(v);
                        g_v_hi[o] = h16; g_v_lo[o] = __float2bfloat16_rn(v - __bfloat162float(h16));
                    }
                }
            }
        }
    }
}

// =====================================================================
// Causal flash attention v2: cp.async 2-stage K/V prefetch, ONE barrier
// per k-tile. smem: Q(32KB) + 2 stages x (Khi,Klo,Vhi,Vlo of 8KB) = 96KB.
// =====================================================================
constexpr int ATTN_SMEM = (16384 + 2 * 16384) * 2;   // 98304 bytes

__global__ __launch_bounds__(256, 2) void attn_mma()
{
    extern __shared__ __align__(16) __nv_bfloat16 dsm[];
    constexpr int QHI = 0, QLO = 8192;

    const int qt = (int)gridDim.x - 1 - (int)blockIdx.x;
    const int bh = blockIdx.y, bb = bh >> 4, hh = bh & 15;
    const size_t base = (size_t)bh * (2048*64);
    const int tid = threadIdx.x, w = tid >> 5, lane = tid & 31;
    const int gid = lane >> 2, tig = lane & 3;
    const uint32_t sbase = (uint32_t)__cvta_generic_to_shared(dsm);
    const int a_r = lane & 15, a_k8 = lane >> 4;
    const int b_r = (lane & 7) + ((lane >> 4) & 1) * 8, b_k8 = (lane >> 3) & 1;

    // K/V stage loader: 4 planes x 64 rows x 8 cells(16B) = 2048 chunks, 8/thread
    auto issue_kv = [&](int kt) {
        const uint32_t sbuf = sbase + (uint32_t)(16384 + (kt & 1) * 16384) * 2;
        const __nv_bfloat16* bases[4] = { g_k_hi + base, g_k_lo + base, g_v_hi + base, g_v_lo + base };
        #pragma unroll
        for (int i = 0; i < 8; i++) {
            const int u = tid + 256 * i;
            const int plane = u >> 9, rem = u & 511;
            const int row = rem >> 3, c16 = rem & 7;
            const uint32_t so = (uint32_t)(row * 128 + ((c16 ^ (row & 7)) * 16));
            const size_t goff = (plane < 2)
                ? ((size_t)(kt * 64 + row) * 64 + c16 * 8)
                : ((size_t)row * 2048 + (size_t)kt * 64 + c16 * 8);
            cp_async16(sbuf + (uint32_t)plane * 8192u + so, bases[plane] + goff);
        }
        cp_commit();
    };

    // load Q tile (128 x 64), both planes (plain loads; published by first barrier)
    #pragma unroll
    for (int it = 0; it < 4; it++) {
        const int u = tid + 256*it, r = u >> 3, c16 = u & 7;
        const int so = r*64 + ((c16 ^ (r & 7))*8);
        const size_t go = base + (size_t)(qt*128 + r)*64 + c16*8;
        *(uint4*)&dsm[QHI + so] = *(const uint4*)(g_q_hi + go);
        *(uint4*)&dsm[QLO + so] = *(const uint4*)(g_q_lo + go);
    }

    float s[8][4], o[8][4] = {};
    float mr0 = -1e30f, mr1 = -1e30f, lr0 = 0.f, lr1 = 0.f;
    const int row0g = qt*128 + w*16 + gid, row1g = row0g + 8;
    const int ntiles = 2*qt + 2;

    issue_kv(0);

    for (int kt = 0; kt < ntiles; kt++) {
        cp_wait<0>();
        __syncthreads();              // kt data visible to all; all warps done with kt-1
        if (kt + 1 < ntiles) issue_kv(kt + 1);

        const int khi = 16384 + (kt & 1) * 16384;
        const int klo = khi + 4096, vhi = khi + 8192, vlo = khi + 12288;

        #pragma unroll
        for (int j = 0; j < 8; j++)
            #pragma unroll
            for (int r = 0; r < 4; r++) s[j][r] = 0.f;
        #pragma unroll
        for (int kk = 0; kk < 4; kk++) {
            uint32_t aqh[4], aql[4];
            {
                const int r = w*16 + a_r, c16 = kk*2 + a_k8;
                const int so = r*64 + ((c16 ^ (r & 7))*8);
                ldsm4(sbase + (uint32_t)(QHI + so)*2, aqh[0], aqh[1], aqh[2], aqh[3]);
                ldsm4(sbase + (uint32_t)(QLO + so)*2, aql[0], aql[1], aql[2], aql[3]);
            }
            uint32_t bk[2][4][4];
            #pragma unroll
            for (int g = 0; g < 4; g++) {
                const int r = g*16 + b_r, c16 = kk*2 + b_k8;
                const int so = r*64 + ((c16 ^ (r & 7))*8);
                ldsm4(sbase + (uint32_t)(khi + so)*2, bk[0][g][0], bk[0][g][1], bk[0][g][2], bk[0][g][3]);
                ldsm4(sbase + (uint32_t)(klo + so)*2, bk[1][g][0], bk[1][g][1], bk[1][g][2], bk[1][g][3]);
            }
            #pragma unroll
            for (int j8 = 0; j8 < 8; j8++) {
                const int g = j8 >> 1, h = (j8 & 1)*2;
                mma16816(s[j8], aqh, bk[0][g][h], bk[0][g][h+1]);
                mma16816(s[j8], aqh, bk[1][g][h], bk[1][g][h+1]);
                mma16816(s[j8], aql, bk[0][g][h], bk[0][g][h+1]);
            }
        }

        if (kt >= 2*qt) {
            #pragma unroll
            for (int j8 = 0; j8 < 8; j8++) {
                const int c = kt*64 + j8*8 + tig*2;
                if (c > row0g)   s[j8][0] = -1e30f;
                if (c+1 > row0g) s[j8][1] = -1e30f;
                if (c > row1g)   s[j8][2] = -1e30f;
                if (c+1 > row1g) s[j8][3] = -1e30f;
            }
        }

        float mx0 = -1e30f, mx1 = -1e30f;
        #pragma unroll
        for (int j8 = 0; j8 < 8; j8++) {
            mx0 = fmaxf(mx0, fmaxf(s[j8][0], s[j8][1]));
            mx1 = fmaxf(mx1, fmaxf(s[j8][2], s[j8][3]));
        }
        mx0 = fmaxf(mx0, __shfl_xor_sync(~0u, mx0, 1)); mx0 = fmaxf(mx0, __shfl_xor_sync(~0u, mx0, 2));
        mx1 = fmaxf(mx1, __shfl_xor_sync(~0u, mx1, 1)); mx1 = fmaxf(mx1, __shfl_xor_sync(~0u, mx1, 2));
        const float mn0 = fmaxf(mr0, mx0), mn1 = fmaxf(mr1, mx1);
        const float f0 = __expf(mr0 - mn0), f1 = __expf(mr1 - mn1);
        mr0 = mn0; mr1 = mn1;
        float s0 = 0.f, s1 = 0.f;
        #pragma unroll
        for (int j8 = 0; j8 < 8; j8++) {
            s[j8][0] = __expf(s[j8][0] - mn0); s[j8][1] = __expf(s[j8][1] - mn0);
            s[j8][2] = __expf(s[j8][2] - mn1); s[j8][3] = __expf(s[j8][3] - mn1);
            s0 += s[j8][0] + s[j8][1]; s1 += s[j8][2] + s[j8][3];
        }
        s0 += __shfl_xor_sync(~0u, s0, 1); s0 += __shfl_xor_sync(~0u, s0, 2);
        s1 += __shfl_xor_sync(~0u, s1, 1); s1 += __shfl_xor_sync(~0u, s1, 2);
        lr0 = lr0*f0 + s0; lr1 = lr1*f1 + s1;
        #pragma unroll
        for (int j8 = 0; j8 < 8; j8++) {
            o[j8][0] *= f0; o[j8][1] *= f0; o[j8][2] *= f1; o[j8][3] *= f1;
        }

        #pragma unroll
        for (int kk = 0; kk < 4; kk++) {
            uint32_t aph[4], apl[4];
            split2(s[2*kk][0],   s[2*kk][1],   aph[0], apl[0]);
            split2(s[2*kk][2],   s[2*kk][3],   aph[1], apl[1]);
            split2(s[2*kk+1][0], s[2*kk+1][1], aph[2], apl[2]);
            split2(s[2*kk+1][2], s[2*kk+1][3], aph[3], apl[3]);
            uint32_t bv[2][4][4];
            #pragma unroll
            for (int g = 0; g < 4; g++) {
                const int r = g*16 + b_r, c16 = kk*2 + b_k8;
                const int so = r*64 + ((c16 ^ (r & 7))*8);
                ldsm4(sbase + (uint32_t)(vhi + so)*2, bv[0][g][0], bv[0][g][1], bv[0][g][2], bv[0][g][3]);
                ldsm4(sbase + (uint32_t)(vlo + so)*2, bv[1][g][0], bv[1][g][1], bv[1][g][2], bv[1][g][3]);
            }
            #pragma unroll
            for (int j8 = 0; j8 < 8; j8++) {
                const int g = j8 >> 1, h = (j8 & 1)*2;
                mma16816(o[j8], aph, bv[0][g][h], bv[0][g][h+1]);
                mma16816(o[j8], aph, bv[1][g][h], bv[1][g][h+1]);
                mma16816(o[j8], apl, bv[0][g][h], bv[0][g][h+1]);
            }
        }
    }

    const float i0 = 1.f / lr0, i1 = 1.f / lr1;
    #pragma unroll
    for (int j8 = 0; j8 < 8; j8++) {
        const int col = hh*64 + j8*8 + tig*2;
        uint32_t hi, lo;
        size_t ob = ((size_t)bb*2048 + row0g) * DM + col;
        split2(o[j8][0]*i0, o[j8][1]*i0, hi, lo);
        *(uint32_t*)&g_att_hi[ob] = hi; *(uint32_t*)&g_att_lo[ob] = lo;
        ob = ((size_t)bb*2048 + row1g) * DM + col;
        split2(o[j8][2]*i1, o[j8][3]*i1, hi, lo);
        *(uint32_t*)&g_att_hi[ob] = hi; *(uint32_t*)&g_att_lo[ob] = lo;
    }
}

extern "C" void kernel_launch(void* const* d_in, const int* in_sizes, int n_in,
                              void* d_out, int out_size)
{
    (void)in_sizes; (void)n_in; (void)out_size;
    const float* x      = (const float*)d_in[0];
    const float* w_qkv  = (const float*)d_in[1];
    const float* w_proj = (const float*)d_in[2];
    float* out = (float*)d_out;

    static bool attr_done = false;
    if (!attr_done) {
        cudaFuncSetAttribute(attn_mma, cudaFuncAttributeMaxDynamicSharedMemorySize, ATTN_SMEM);
        cudaFuncSetAttribute(mma_gemm, cudaFuncAttributeMaxDynamicSharedMemorySize, GEMM_SMEM);
        attr_done = true;
    }

    split_x_kernel<<<MROWS*DM/256, 256>>>(x);
    split_wt_kernel<<<dim3(96, 32), 256>>>(w_qkv, 3*DM, 0);
    split_wt_kernel<<<dim3(32, 32), 256>>>(w_proj, DM, 1);
    mma_gemm<<<dim3(24, 32), 256, GEMM_SMEM>>>(nullptr, 0);
    attn_mma<<<dim3(16, 32), 256, ATTN_SMEM>>>();
    mma_gemm<<<dim3(8, 32), 256, GEMM_SMEM>>>(out, 1);
}